// round 1
// baseline (speedup 1.0000x reference)
#include <cuda_runtime.h>
#include <math.h>

// ---------------------------------------------------------------------------
// Problem dims (fixed by the reference): B=8, L=2048, D=768
// ---------------------------------------------------------------------------
#define BATCH 8
#define SEQ   2048
#define DIM   768
#define TOK   (BATCH * SEQ)          // 16384

// Scratch (device globals: allocation-free rule)
__device__ float g_vp [TOK * DIM];               // [16384,768]
__device__ float g_lp [TOK * DIM];               // [16384,768]
__device__ float g_sim[(long)BATCH * SEQ * SEQ]; // [8,2048,2048] -> becomes attn in-place
__device__ float g_av [TOK * DIM];
__device__ float g_al [TOK * DIM];

// ---------------------------------------------------------------------------
// Generic 128x128x16 fp32 tiled GEMM.
//   C[m,n] (+)= sum_k op(A)[m,k] * op(B)[k,n]  (+ bias[n])
//   op(A)[m,k] = TA ? A[k*lda+m] : A[m*lda+k]
//   op(B)[k,n] = TB ? B[n*ldb+k] : B[k*ldb+n]
// Requires: M%128==0, N%128==0, K%16==0, all leading dims %4==0.
// blockIdx.z = batch index with element strides sA/sB/sC.
// ---------------------------------------------------------------------------
template<bool TA, bool TB, bool BETA, bool BIAS>
__global__ __launch_bounds__(256)
void gemm128(const float* __restrict__ A, int lda, long sA,
             const float* __restrict__ B, int ldb, long sB,
             float* __restrict__ C, int ldc, long sC,
             int K, const float* __restrict__ bias)
{
    __shared__ float As[16][128];
    __shared__ float Bs[16][128];

    A += (long)blockIdx.z * sA;
    B += (long)blockIdx.z * sB;
    C += (long)blockIdx.z * sC;

    const int tid = threadIdx.x;
    const int tx  = tid & 15;
    const int ty  = tid >> 4;
    const long m0 = (long)blockIdx.y * 128;
    const long n0 = (long)blockIdx.x * 128;

    float acc[8][8];
#pragma unroll
    for (int i = 0; i < 8; ++i)
#pragma unroll
        for (int j = 0; j < 8; ++j) acc[i][j] = 0.f;

    for (int k0 = 0; k0 < K; k0 += 16) {
        // ---- load A tile -> As[k][m], B tile -> Bs[k][n] (float4 global) ----
#pragma unroll
        for (int p = 0; p < 2; ++p) {
            const int lin = tid + p * 256;
            if (!TA) {
                const int row = lin >> 2;
                const int kq  = (lin & 3) * 4;
                float4 v = *reinterpret_cast<const float4*>(&A[(m0 + row) * lda + k0 + kq]);
                As[kq + 0][row] = v.x; As[kq + 1][row] = v.y;
                As[kq + 2][row] = v.z; As[kq + 3][row] = v.w;
            } else {
                const int k  = lin >> 5;
                const int mq = (lin & 31) * 4;
                float4 v = *reinterpret_cast<const float4*>(&A[(long)(k0 + k) * lda + m0 + mq]);
                *reinterpret_cast<float4*>(&As[k][mq]) = v;
            }
            if (!TB) {
                const int k  = lin >> 5;
                const int nq = (lin & 31) * 4;
                float4 v = *reinterpret_cast<const float4*>(&B[(long)(k0 + k) * ldb + n0 + nq]);
                *reinterpret_cast<float4*>(&Bs[k][nq]) = v;
            } else {
                const int col = lin >> 2;
                const int kq  = (lin & 3) * 4;
                float4 v = *reinterpret_cast<const float4*>(&B[(n0 + col) * ldb + k0 + kq]);
                Bs[kq + 0][col] = v.x; Bs[kq + 1][col] = v.y;
                Bs[kq + 2][col] = v.z; Bs[kq + 3][col] = v.w;
            }
        }
        __syncthreads();

        // ---- 16 rank-1 updates, split 4+4 fragments (conflict-free LDS.128) ----
#pragma unroll
        for (int kk = 0; kk < 16; ++kk) {
            float4 a0 = *reinterpret_cast<const float4*>(&As[kk][ty * 4]);
            float4 a1 = *reinterpret_cast<const float4*>(&As[kk][64 + ty * 4]);
            float4 b0 = *reinterpret_cast<const float4*>(&Bs[kk][tx * 4]);
            float4 b1 = *reinterpret_cast<const float4*>(&Bs[kk][64 + tx * 4]);
            const float a[8] = {a0.x, a0.y, a0.z, a0.w, a1.x, a1.y, a1.z, a1.w};
            const float b[8] = {b0.x, b0.y, b0.z, b0.w, b1.x, b1.y, b1.z, b1.w};
#pragma unroll
            for (int i = 0; i < 8; ++i)
#pragma unroll
                for (int j = 0; j < 8; ++j)
                    acc[i][j] = fmaf(a[i], b[j], acc[i][j]);
        }
        __syncthreads();
    }

    // ---- epilogue ----
#pragma unroll
    for (int i = 0; i < 8; ++i) {
        const long m = m0 + ((i < 4) ? (ty * 4 + i) : (64 + ty * 4 + i - 4));
#pragma unroll
        for (int jh = 0; jh < 2; ++jh) {
            const long n = n0 + ((jh == 0) ? (tx * 4) : (64 + tx * 4));
            float4 v = make_float4(acc[i][jh * 4 + 0], acc[i][jh * 4 + 1],
                                   acc[i][jh * 4 + 2], acc[i][jh * 4 + 3]);
            if (BIAS) {
                float4 bb = *reinterpret_cast<const float4*>(&bias[n]);
                v.x += bb.x; v.y += bb.y; v.z += bb.z; v.w += bb.w;
            }
            if (BETA) {
                float4 c = *reinterpret_cast<const float4*>(&C[m * ldc + n]);
                v.x += c.x; v.y += c.y; v.z += c.z; v.w += c.w;
            }
            *reinterpret_cast<float4*>(&C[m * ldc + n]) = v;
        }
    }
}

// ---------------------------------------------------------------------------
// Row softmax, in place. One block (256 threads) per row of 2048 fp32.
// ---------------------------------------------------------------------------
__global__ __launch_bounds__(256)
void softmax2048(float* __restrict__ S)
{
    float* p = S + (long)blockIdx.x * 2048;
    const int tid = threadIdx.x;

    float4 v0 = reinterpret_cast<float4*>(p)[tid];
    float4 v1 = reinterpret_cast<float4*>(p)[tid + 256];

    float mx = fmaxf(fmaxf(fmaxf(v0.x, v0.y), fmaxf(v0.z, v0.w)),
                     fmaxf(fmaxf(v1.x, v1.y), fmaxf(v1.z, v1.w)));

    __shared__ float red[8];
#pragma unroll
    for (int o = 16; o > 0; o >>= 1) mx = fmaxf(mx, __shfl_xor_sync(0xffffffffu, mx, o));
    if ((tid & 31) == 0) red[tid >> 5] = mx;
    __syncthreads();
    if (tid == 0) {
        float m = red[0];
#pragma unroll
        for (int w = 1; w < 8; ++w) m = fmaxf(m, red[w]);
        red[0] = m;
    }
    __syncthreads();
    mx = red[0];
    __syncthreads();

    v0.x = __expf(v0.x - mx); v0.y = __expf(v0.y - mx);
    v0.z = __expf(v0.z - mx); v0.w = __expf(v0.w - mx);
    v1.x = __expf(v1.x - mx); v1.y = __expf(v1.y - mx);
    v1.z = __expf(v1.z - mx); v1.w = __expf(v1.w - mx);

    float s = (v0.x + v0.y + v0.z + v0.w) + (v1.x + v1.y + v1.z + v1.w);
#pragma unroll
    for (int o = 16; o > 0; o >>= 1) s += __shfl_xor_sync(0xffffffffu, s, o);
    if ((tid & 31) == 0) red[tid >> 5] = s;
    __syncthreads();
    if (tid == 0) {
        float t = 0.f;
#pragma unroll
        for (int w = 0; w < 8; ++w) t += red[w];
        red[0] = t;
    }
    __syncthreads();
    const float inv = 1.0f / red[0];

    v0.x *= inv; v0.y *= inv; v0.z *= inv; v0.w *= inv;
    v1.x *= inv; v1.y *= inv; v1.z *= inv; v1.w *= inv;
    reinterpret_cast<float4*>(p)[tid]       = v0;
    reinterpret_cast<float4*>(p)[tid + 256] = v1;
}

// ---------------------------------------------------------------------------
// Launch
// ---------------------------------------------------------------------------
extern "C" void kernel_launch(void* const* d_in, const int* in_sizes, int n_in,
                              void* d_out, int out_size)
{
    const float* Vf = (const float*)d_in[0];
    const float* Lf = (const float*)d_in[1];
    const float* Wv = (const float*)d_in[2];
    const float* bv = (const float*)d_in[3];
    const float* Wl = (const float*)d_in[4];
    const float* bl = (const float*)d_in[5];
    const float* Wo = (const float*)d_in[6];
    const float* bo = (const float*)d_in[7];
    float* out = (float*)d_out;

    float *vp, *lp, *sim, *av, *al;
    cudaGetSymbolAddress((void**)&vp,  g_vp);
    cudaGetSymbolAddress((void**)&lp,  g_lp);
    cudaGetSymbolAddress((void**)&sim, g_sim);
    cudaGetSymbolAddress((void**)&av,  g_av);
    cudaGetSymbolAddress((void**)&al,  g_al);

    const dim3 blk(256);
    const long sS = (long)SEQ * SEQ;   // sim batch stride
    const long sF = (long)SEQ * DIM;   // feature batch stride

    // vp = Vf @ Wv^T + bv   [16384,768]
    gemm128<false, true, false, true><<<dim3(DIM/128, TOK/128, 1), blk>>>(
        Vf, DIM, 0, Wv, DIM, 0, vp, DIM, 0, DIM, bv);
    // lp = Lf @ Wl^T + bl
    gemm128<false, true, false, true><<<dim3(DIM/128, TOK/128, 1), blk>>>(
        Lf, DIM, 0, Wl, DIM, 0, lp, DIM, 0, DIM, bl);
    // sim[b] = vp_b @ lp_b^T   [8,2048,2048]
    gemm128<false, true, false, false><<<dim3(SEQ/128, SEQ/128, BATCH), blk>>>(
        vp, DIM, sF, lp, DIM, sF, sim, SEQ, sS, DIM, nullptr);
    // attn = softmax(sim) in place
    softmax2048<<<TOK, blk>>>(sim);
    // av[b] = attn_b @ vp_b    [8,2048,768]
    gemm128<false, false, false, false><<<dim3(DIM/128, SEQ/128, BATCH), blk>>>(
        sim, SEQ, sS, vp, DIM, sF, av, DIM, sF, SEQ, nullptr);
    // al[b] = attn_b^T @ lp_b  [8,2048,768]
    gemm128<true, false, false, false><<<dim3(DIM/128, SEQ/128, BATCH), blk>>>(
        sim, SEQ, sS, lp, DIM, sF, al, DIM, sF, SEQ, nullptr);
    // out = av @ Wo[:, :768]^T + bo
    gemm128<false, true, false, true><<<dim3(DIM/128, TOK/128, 1), blk>>>(
        av, DIM, 0, Wo, 2 * DIM, 0, out, DIM, 0, DIM, bo);
    // out += al @ Wo[:, 768:]^T
    gemm128<false, true, true, false><<<dim3(DIM/128, TOK/128, 1), blk>>>(
        al, DIM, 0, Wo + DIM, 2 * DIM, 0, out, DIM, 0, DIM, nullptr);
}

// round 3
// speedup vs baseline: 1.1593x; 1.1593x over previous
#include <cuda_runtime.h>
#include <cstdint>

// ---------------------------------------------------------------------------
// B=8, L=2048, D=768.  3xTF32 mma.sync GEMMs + fp32 softmax.
// (tcgen05 is unavailable: harness PTX target is plain sm_103)
// ---------------------------------------------------------------------------
#define BATCH 8
#define SEQ   2048
#define DIM   768
#define TOK   (BATCH * SEQ)          // 16384

// Scratch (device globals: allocation-free rule)
__device__ float g_vp [TOK * DIM];                 // [16384,768]
__device__ float g_lp [TOK * DIM];                 // [16384,768]
__device__ float g_sim[(long)BATCH * SEQ * SEQ];   // [8,2048,2048] -> attn in place
__device__ float g_comb[(long)TOK * 2 * DIM];      // [16384,1536]  av | al

// ---------------------------------------------------------------------------
// helpers
// ---------------------------------------------------------------------------
__device__ __forceinline__ uint32_t smem_u32(const void* p) {
    uint32_t a;
    asm("{ .reg .u64 t; cvta.to.shared.u64 t, %1; cvt.u32.u64 %0, t; }"
        : "=r"(a) : "l"(p));
    return a;
}
__device__ __forceinline__ void cp16(uint32_t s, const void* g) {
    asm volatile("cp.async.ca.shared.global [%0], [%1], 16;" :: "r"(s), "l"(g));
}
#define CP_COMMIT() asm volatile("cp.async.commit_group;" ::: "memory")
#define CP_WAIT1()  asm volatile("cp.async.wait_group 1;" ::: "memory")

// fp32 -> (hi, lo) tf32 pair, results kept as b32 for mma operands
__device__ __forceinline__ void split1(float a, uint32_t& h, uint32_t& l) {
    asm("cvt.rna.tf32.f32 %0, %1;" : "=r"(h) : "f"(a));
    float r = a - __uint_as_float(h);
    asm("cvt.rna.tf32.f32 %0, %1;" : "=r"(l) : "f"(r));
}

__device__ __forceinline__ void mma8(float* d, const uint32_t* a, const uint32_t* b) {
    asm volatile(
        "mma.sync.aligned.m16n8k8.row.col.f32.tf32.tf32.f32 "
        "{%0,%1,%2,%3}, {%4,%5,%6,%7}, {%8,%9}, {%0,%1,%2,%3};"
        : "+f"(d[0]), "+f"(d[1]), "+f"(d[2]), "+f"(d[3])
        : "r"(a[0]), "r"(a[1]), "r"(a[2]), "r"(a[3]), "r"(b[0]), "r"(b[1]));
}

// ---------------------------------------------------------------------------
// Stage loader: 128 rows x 32 k of fp32 -> smem [row][k] with stride 36.
//   TR=false: G[(row0+r)*ld + k0+k]   (cp.async, 16B)
//   TR=true : G[(k0+k)*ld + row0+r]   (coalesced LDG.32 -> STS)
// 256 threads.
// ---------------------------------------------------------------------------
template<bool TR>
__device__ __forceinline__ void load_stage(const float* __restrict__ G, int ld,
                                           long row0, int k0,
                                           float* Ss, int tid)
{
    if (!TR) {
#pragma unroll
        for (int p = 0; p < 4; ++p) {
            const int idx = tid + p * 256;        // 0..1023
            const int r   = idx >> 3;             // 0..127
            const int c4  = (idx & 7) * 4;        // 0..28
            cp16(smem_u32(&Ss[r * 36 + c4]), &G[(row0 + r) * (long)ld + k0 + c4]);
        }
    } else {
#pragma unroll
        for (int p = 0; p < 4; ++p) {
            const int idx = tid + p * 256;        // 0..1023
            const int m   = idx & 127;
            const int kg  = (idx >> 7) * 4;       // 0,4,...,28
#pragma unroll
            for (int j = 0; j < 4; ++j)
                Ss[m * 36 + kg + j] = G[(long)(k0 + kg + j) * ld + row0 + m];
        }
    }
}

// ---------------------------------------------------------------------------
// 3xTF32 GEMM via mma.sync, CTA tile 128x128, K-chunk 32, 3-stage cp.async.
//   C[m,n] = sum_k opA[m,k]*opB[n,k] (+ bias[n])
//   opA[m,k] = TA ? A[k*lda+m] : A[m*lda+k]
//   opB[n,k] = TB ? B[k*ldb+n] : B[n*ldb+k]
// Dynamic SMEM: 3 stages x 2 tiles x 128*36*4B = 110592 B
// ---------------------------------------------------------------------------
#define TILE_F  (128 * 36)           // floats per tile
#define STAGE_F (2 * TILE_F)         // A tile + B tile

template<bool TA, bool TB, bool BIAS>
__global__ __launch_bounds__(256)
void tgemm(const float* __restrict__ A, int lda, long sA,
           const float* __restrict__ B, int ldb, long sB,
           float* __restrict__ C, int ldc, long sC,
           int K, const float* __restrict__ bias)
{
    extern __shared__ float dsm[];

    A += (long)blockIdx.z * sA;
    B += (long)blockIdx.z * sB;
    C += (long)blockIdx.z * sC;

    const int tid  = threadIdx.x;
    const int lane = tid & 31;
    const int wid  = tid >> 5;
    const int wm   = wid & 3;         // 4 warps along M: 32 rows each
    const int wn   = wid >> 2;        // 2 warps along N: 64 cols each
    const long m0  = (long)blockIdx.y * 128;
    const long n0  = (long)blockIdx.x * 128;

    float acc[2][8][4];
#pragma unroll
    for (int i = 0; i < 2; ++i)
#pragma unroll
        for (int j = 0; j < 8; ++j)
#pragma unroll
            for (int q = 0; q < 4; ++q) acc[i][j][q] = 0.f;

    const int NIT = K / 32;

    // prologue: stages 0,1
    load_stage<TA>(A, lda, m0, 0, dsm,          tid);
    load_stage<TB>(B, ldb, n0, 0, dsm + TILE_F, tid);
    CP_COMMIT();
    if (NIT > 1) {
        load_stage<TA>(A, lda, m0, 32, dsm + STAGE_F,          tid);
        load_stage<TB>(B, ldb, n0, 32, dsm + STAGE_F + TILE_F, tid);
    }
    CP_COMMIT();

    const int lr = lane >> 2;   // 0..7
    const int lc = lane & 3;    // 0..3

    for (int it = 0; it < NIT; ++it) {
        CP_WAIT1();
        __syncthreads();

        const float* As = dsm + (it % 3) * STAGE_F;
        const float* Bs = As + TILE_F;

        // ---- compute this stage: 4 ksteps of k=8 ----
#pragma unroll
        for (int ks = 0; ks < 4; ++ks) {
            const int kb = ks * 8;
            // A fragments for 2 m-tiles (raw -> hi/lo)
            uint32_t ah[2][4], al[2][4];
#pragma unroll
            for (int mt = 0; mt < 2; ++mt) {
                const int mb = wm * 32 + mt * 16;
                float r0 = As[(mb + lr)     * 36 + kb + lc];
                float r1 = As[(mb + 8 + lr) * 36 + kb + lc];
                float r2 = As[(mb + lr)     * 36 + kb + 4 + lc];
                float r3 = As[(mb + 8 + lr) * 36 + kb + 4 + lc];
                split1(r0, ah[mt][0], al[mt][0]);
                split1(r1, ah[mt][1], al[mt][1]);
                split1(r2, ah[mt][2], al[mt][2]);
                split1(r3, ah[mt][3], al[mt][3]);
            }
#pragma unroll
            for (int nt = 0; nt < 8; ++nt) {
                const int nb = wn * 64 + nt * 8;
                uint32_t bh[2], bl[2];
                float s0 = Bs[(nb + lr) * 36 + kb + lc];
                float s1 = Bs[(nb + lr) * 36 + kb + 4 + lc];
                split1(s0, bh[0], bl[0]);
                split1(s1, bh[1], bl[1]);
#pragma unroll
                for (int mt = 0; mt < 2; ++mt) {
                    mma8(acc[mt][nt], ah[mt], bh);
                    mma8(acc[mt][nt], ah[mt], bl);
                    mma8(acc[mt][nt], al[mt], bh);
                }
            }
        }

        // ---- issue loads for stage it+2 ----
        if (it + 2 < NIT) {
            float* st = dsm + ((it + 2) % 3) * STAGE_F;
            load_stage<TA>(A, lda, m0, (it + 2) * 32, st,          tid);
            load_stage<TB>(B, ldb, n0, (it + 2) * 32, st + TILE_F, tid);
        }
        CP_COMMIT();
    }

    // ---- epilogue ----
#pragma unroll
    for (int mt = 0; mt < 2; ++mt) {
        const long r0 = m0 + wm * 32 + mt * 16 + lr;
#pragma unroll
        for (int nt = 0; nt < 8; ++nt) {
            const long c = n0 + wn * 64 + nt * 8 + lc * 2;
            float2 v0 = make_float2(acc[mt][nt][0], acc[mt][nt][1]);
            float2 v1 = make_float2(acc[mt][nt][2], acc[mt][nt][3]);
            if (BIAS) {
                float2 bb = *reinterpret_cast<const float2*>(&bias[c]);
                v0.x += bb.x; v0.y += bb.y;
                v1.x += bb.x; v1.y += bb.y;
            }
            *reinterpret_cast<float2*>(&C[r0 * ldc + c])       = v0;
            *reinterpret_cast<float2*>(&C[(r0 + 8) * ldc + c]) = v1;
        }
    }
}

// ---------------------------------------------------------------------------
// Row softmax, in place. One block (256 threads) per row of 2048 fp32.
// ---------------------------------------------------------------------------
__global__ __launch_bounds__(256)
void softmax2048(float* __restrict__ S)
{
    float* p = S + (long)blockIdx.x * 2048;
    const int tid = threadIdx.x;

    float4 v0 = reinterpret_cast<float4*>(p)[tid];
    float4 v1 = reinterpret_cast<float4*>(p)[tid + 256];

    float mx = fmaxf(fmaxf(fmaxf(v0.x, v0.y), fmaxf(v0.z, v0.w)),
                     fmaxf(fmaxf(v1.x, v1.y), fmaxf(v1.z, v1.w)));

    __shared__ float red[8];
#pragma unroll
    for (int o = 16; o > 0; o >>= 1) mx = fmaxf(mx, __shfl_xor_sync(0xffffffffu, mx, o));
    if ((tid & 31) == 0) red[tid >> 5] = mx;
    __syncthreads();
    if (tid == 0) {
        float m = red[0];
#pragma unroll
        for (int w = 1; w < 8; ++w) m = fmaxf(m, red[w]);
        red[0] = m;
    }
    __syncthreads();
    mx = red[0];
    __syncthreads();

    v0.x = __expf(v0.x - mx); v0.y = __expf(v0.y - mx);
    v0.z = __expf(v0.z - mx); v0.w = __expf(v0.w - mx);
    v1.x = __expf(v1.x - mx); v1.y = __expf(v1.y - mx);
    v1.z = __expf(v1.z - mx); v1.w = __expf(v1.w - mx);

    float s = (v0.x + v0.y + v0.z + v0.w) + (v1.x + v1.y + v1.z + v1.w);
#pragma unroll
    for (int o = 16; o > 0; o >>= 1) s += __shfl_xor_sync(0xffffffffu, s, o);
    if ((tid & 31) == 0) red[tid >> 5] = s;
    __syncthreads();
    if (tid == 0) {
        float t = 0.f;
#pragma unroll
        for (int w = 0; w < 8; ++w) t += red[w];
        red[0] = t;
    }
    __syncthreads();
    const float inv = 1.0f / red[0];

    v0.x *= inv; v0.y *= inv; v0.z *= inv; v0.w *= inv;
    v1.x *= inv; v1.y *= inv; v1.z *= inv; v1.w *= inv;
    reinterpret_cast<float4*>(p)[tid]       = v0;
    reinterpret_cast<float4*>(p)[tid + 256] = v1;
}

// ---------------------------------------------------------------------------
// Launch
// ---------------------------------------------------------------------------
extern "C" void kernel_launch(void* const* d_in, const int* in_sizes, int n_in,
                              void* d_out, int out_size)
{
    const float* Vf = (const float*)d_in[0];
    const float* Lf = (const float*)d_in[1];
    const float* Wv = (const float*)d_in[2];
    const float* bv = (const float*)d_in[3];
    const float* Wl = (const float*)d_in[4];
    const float* bl = (const float*)d_in[5];
    const float* Wo = (const float*)d_in[6];
    const float* bo = (const float*)d_in[7];
    float* out = (float*)d_out;

    float *vp, *lp, *sim, *comb;
    cudaGetSymbolAddress((void**)&vp,   g_vp);
    cudaGetSymbolAddress((void**)&lp,   g_lp);
    cudaGetSymbolAddress((void**)&sim,  g_sim);
    cudaGetSymbolAddress((void**)&comb, g_comb);

    const size_t SMEM = 3 * STAGE_F * sizeof(float);   // 110592
    cudaFuncSetAttribute(tgemm<false, false, true >, cudaFuncAttributeMaxDynamicSharedMemorySize, SMEM);
    cudaFuncSetAttribute(tgemm<false, false, false>, cudaFuncAttributeMaxDynamicSharedMemorySize, SMEM);
    cudaFuncSetAttribute(tgemm<false, true,  false>, cudaFuncAttributeMaxDynamicSharedMemorySize, SMEM);
    cudaFuncSetAttribute(tgemm<true,  true,  false>, cudaFuncAttributeMaxDynamicSharedMemorySize, SMEM);

    const dim3 blk(256);
    const long sS = (long)SEQ * SEQ;     // sim batch stride
    const long sF = (long)SEQ * DIM;     // feature batch stride
    const long sO = (long)SEQ * 2 * DIM; // comb batch stride

    // vp = Vf @ Wv^T + bv   [16384,768]
    tgemm<false, false, true><<<dim3(DIM/128, TOK/128, 1), blk, SMEM>>>(
        Vf, DIM, 0, Wv, DIM, 0, vp, DIM, 0, DIM, bv);
    // lp = Lf @ Wl^T + bl
    tgemm<false, false, true><<<dim3(DIM/128, TOK/128, 1), blk, SMEM>>>(
        Lf, DIM, 0, Wl, DIM, 0, lp, DIM, 0, DIM, bl);
    // sim[b] = vp_b @ lp_b^T   [8,2048,2048]
    tgemm<false, false, false><<<dim3(SEQ/128, SEQ/128, BATCH), blk, SMEM>>>(
        vp, DIM, sF, lp, DIM, sF, sim, SEQ, sS, DIM, nullptr);
    // attn = softmax(sim) in place
    softmax2048<<<TOK, blk>>>(sim);
    // comb[:, :768] = av[b] = attn_b @ vp_b   (opB[n,k]=vp[k*DIM+n] -> TB)
    tgemm<false, true, false><<<dim3(DIM/128, SEQ/128, BATCH), blk, SMEM>>>(
        sim, SEQ, sS, vp, DIM, sF, comb, 2 * DIM, sO, SEQ, nullptr);
    // comb[:, 768:] = al[b] = attn_b^T @ lp_b (TA; opB[n,k]=lp[k*DIM+n] -> TB)
    tgemm<true, true, false><<<dim3(DIM/128, SEQ/128, BATCH), blk, SMEM>>>(
        sim, SEQ, sS, lp, DIM, sF, comb + DIM, 2 * DIM, sO, SEQ, nullptr);
    // out = comb @ Wo^T + bo   (K=1536)
    tgemm<false, false, true><<<dim3(DIM/128, TOK/128, 1), blk, SMEM>>>(
        comb, 2 * DIM, 0, Wo, 2 * DIM, 0, out, DIM, 0, 2 * DIM, bo);
}

// round 4
// speedup vs baseline: 2.1295x; 1.8369x over previous
#include <cuda_runtime.h>
#include <cuda_fp16.h>
#include <cstdint>

// ---------------------------------------------------------------------------
// B=8, L=2048, D=768.  3xFP16 mma.sync(m16n8k16) GEMMs + fp32 softmax.
// ---------------------------------------------------------------------------
#define BATCH 8
#define SEQ   2048
#define DIM   768
#define TOK   (BATCH * SEQ)          // 16384

// Scratch (device globals: allocation-free rule)
__device__ float g_vp [TOK * DIM];                 // [16384,768]
__device__ float g_lp [TOK * DIM];                 // [16384,768]
__device__ float g_sim[(long)BATCH * SEQ * SEQ];   // [8,2048,2048] -> attn in place
__device__ float g_comb[(long)TOK * 2 * DIM];      // [16384,1536]  av | al

// ---------------------------------------------------------------------------
// helpers
// ---------------------------------------------------------------------------
__device__ __forceinline__ void mma16(float* d, const uint32_t* a, const uint32_t* b) {
    asm volatile(
        "mma.sync.aligned.m16n8k16.row.col.f32.f16.f16.f32 "
        "{%0,%1,%2,%3}, {%4,%5,%6,%7}, {%8,%9}, {%0,%1,%2,%3};"
        : "+f"(d[0]), "+f"(d[1]), "+f"(d[2]), "+f"(d[3])
        : "r"(a[0]), "r"(a[1]), "r"(a[2]), "r"(a[3]), "r"(b[0]), "r"(b[1]));
}
__device__ __forceinline__ uint32_t lds_u32(const __half* p) {
    return *reinterpret_cast<const uint32_t*>(p);
}
// fp32 -> hi fp16 + lo fp16 (hi+lo captures ~22 mantissa bits)
__device__ __forceinline__ void split_h(float a, __half& h, __half& l) {
    h = __float2half_rn(a);
    l = __float2half_rn(a - __half2float(h));
}

// SMEM half-tile geometry: 128 rows x 32 k, row stride 40 halves (80 B)
#define ROWH    40
#define TILE_H  (128 * ROWH)          // halves per (hi or lo) tile
#define STAGE_H (4 * TILE_H)          // Ahi|Alo|Bhi|Blo
#define NSTAGE  3
#define SMEM_B  (NSTAGE * STAGE_H * 2) // bytes = 122880

// ---------------------------------------------------------------------------
// Stage LDG into registers (16 floats/thread):
//   TR=false: G[(row0+r)*ld + k0+k]   (float4)
//   TR=true : G[(k0+k)*ld + row0+m]   (coalesced scalar)
// ---------------------------------------------------------------------------
template<bool TR>
__device__ __forceinline__ void ldg_tile(const float* __restrict__ G, int ld,
                                         long row0, int k0, int tid, float* v)
{
    if (!TR) {
#pragma unroll
        for (int p = 0; p < 4; ++p) {
            const int idx = tid + p * 256;
            const int r   = idx >> 3;
            const int c4  = (idx & 7) * 4;
            float4 t = *reinterpret_cast<const float4*>(&G[(row0 + r) * (long)ld + k0 + c4]);
            v[p * 4 + 0] = t.x; v[p * 4 + 1] = t.y;
            v[p * 4 + 2] = t.z; v[p * 4 + 3] = t.w;
        }
    } else {
        const int m = tid & 127;
#pragma unroll
        for (int p = 0; p < 4; ++p) {
            const int kg = ((tid + p * 256) >> 7) * 4;
#pragma unroll
            for (int j = 0; j < 4; ++j)
                v[p * 4 + j] = G[(long)(k0 + kg + j) * ld + row0 + m];
        }
    }
}

// Split + store registers into hi/lo SMEM tiles.
template<bool TR>
__device__ __forceinline__ void sts_tile(const float* v, __half* Shi, __half* Slo, int tid)
{
#pragma unroll
    for (int p = 0; p < 4; ++p) {
        __half h[4], l[4];
#pragma unroll
        for (int j = 0; j < 4; ++j) split_h(v[p * 4 + j], h[j], l[j]);
        int r, c;
        if (!TR) {
            const int idx = tid + p * 256;
            r = idx >> 3; c = (idx & 7) * 4;
        } else {
            r = tid & 127; c = ((tid + p * 256) >> 7) * 4;
        }
        *reinterpret_cast<__half2*>(&Shi[r * ROWH + c])     = __halves2half2(h[0], h[1]);
        *reinterpret_cast<__half2*>(&Shi[r * ROWH + c + 2]) = __halves2half2(h[2], h[3]);
        *reinterpret_cast<__half2*>(&Slo[r * ROWH + c])     = __halves2half2(l[0], l[1]);
        *reinterpret_cast<__half2*>(&Slo[r * ROWH + c + 2]) = __halves2half2(l[2], l[3]);
    }
}

// ---------------------------------------------------------------------------
// 3xFP16 GEMM via mma.sync m16n8k16, CTA tile 128x128, K-chunk 32,
// 3-buffer register-staged pipeline.
//   C[m,n] = sum_k opA[m,k]*opB[n,k] (+ bias[n])
// ---------------------------------------------------------------------------
template<bool TA, bool TB, bool BIAS>
__global__ __launch_bounds__(256)
void tgemm(const float* __restrict__ A, int lda, long sA,
           const float* __restrict__ B, int ldb, long sB,
           float* __restrict__ C, int ldc, long sC,
           int K, const float* __restrict__ bias)
{
    extern __shared__ __half hsm[];

    A += (long)blockIdx.z * sA;
    B += (long)blockIdx.z * sB;
    C += (long)blockIdx.z * sC;

    const int tid  = threadIdx.x;
    const int lane = tid & 31;
    const int wid  = tid >> 5;
    const int wm   = wid & 3;          // 4 warps along M
    const int wn   = wid >> 2;         // 2 warps along N
    const long m0  = (long)blockIdx.y * 128;
    const long n0  = (long)blockIdx.x * 128;
    const int lr   = lane >> 2;        // 0..7
    const int lc   = lane & 3;         // 0..3

    float acc[2][8][4];
#pragma unroll
    for (int i = 0; i < 2; ++i)
#pragma unroll
        for (int j = 0; j < 8; ++j)
#pragma unroll
            for (int q = 0; q < 4; ++q) acc[i][j][q] = 0.f;

    const int NIT = K / 32;
    float ra[16], rb[16];

    // prologue: stage 0 into smem buf0, stage 1 into registers
    ldg_tile<TA>(A, lda, m0, 0, tid, ra);
    ldg_tile<TB>(B, ldb, n0, 0, tid, rb);
    sts_tile<TA>(ra, hsm,              hsm + TILE_H,     tid);
    sts_tile<TB>(rb, hsm + 2 * TILE_H, hsm + 3 * TILE_H, tid);
    if (NIT > 1) {
        ldg_tile<TA>(A, lda, m0, 32, tid, ra);
        ldg_tile<TB>(B, ldb, n0, 32, tid, rb);
    }

    for (int it = 0; it < NIT; ++it) {
        __syncthreads();   // buf[it%3] stores visible; compute(it-1) done

        if (it + 1 < NIT) {
            __half* st = hsm + ((it + 1) % 3) * STAGE_H;
            sts_tile<TA>(ra, st,              st + TILE_H,     tid);
            sts_tile<TB>(rb, st + 2 * TILE_H, st + 3 * TILE_H, tid);
        }
        if (it + 2 < NIT) {
            ldg_tile<TA>(A, lda, m0, (it + 2) * 32, tid, ra);
            ldg_tile<TB>(B, ldb, n0, (it + 2) * 32, tid, rb);
        }

        const __half* Ahi = hsm + (it % 3) * STAGE_H;
        const __half* Alo = Ahi + TILE_H;
        const __half* Bhi = Ahi + 2 * TILE_H;
        const __half* Blo = Ahi + 3 * TILE_H;

#pragma unroll
        for (int ks = 0; ks < 2; ++ks) {
            const int kb = ks * 16;
            uint32_t ah[2][4], al[2][4];
#pragma unroll
            for (int mt = 0; mt < 2; ++mt) {
                const int mb = wm * 32 + mt * 16;
                const int o0 = (mb + lr)     * ROWH + kb + 2 * lc;
                const int o1 = (mb + 8 + lr) * ROWH + kb + 2 * lc;
                ah[mt][0] = lds_u32(&Ahi[o0]);
                ah[mt][1] = lds_u32(&Ahi[o1]);
                ah[mt][2] = lds_u32(&Ahi[o0 + 8]);
                ah[mt][3] = lds_u32(&Ahi[o1 + 8]);
                al[mt][0] = lds_u32(&Alo[o0]);
                al[mt][1] = lds_u32(&Alo[o1]);
                al[mt][2] = lds_u32(&Alo[o0 + 8]);
                al[mt][3] = lds_u32(&Alo[o1 + 8]);
            }
#pragma unroll
            for (int nt = 0; nt < 8; ++nt) {
                const int nb = wn * 64 + nt * 8;
                const int ob = (nb + lr) * ROWH + kb + 2 * lc;
                uint32_t bh[2], bl[2];
                bh[0] = lds_u32(&Bhi[ob]);
                bh[1] = lds_u32(&Bhi[ob + 8]);
                bl[0] = lds_u32(&Blo[ob]);
                bl[1] = lds_u32(&Blo[ob + 8]);
#pragma unroll
                for (int mt = 0; mt < 2; ++mt) {
                    mma16(acc[mt][nt], ah[mt], bh);
                    mma16(acc[mt][nt], ah[mt], bl);
                    mma16(acc[mt][nt], al[mt], bh);
                }
            }
        }
    }

    // ---- epilogue ----
#pragma unroll
    for (int mt = 0; mt < 2; ++mt) {
        const long r0 = m0 + wm * 32 + mt * 16 + lr;
#pragma unroll
        for (int nt = 0; nt < 8; ++nt) {
            const long c = n0 + wn * 64 + nt * 8 + lc * 2;
            float2 v0 = make_float2(acc[mt][nt][0], acc[mt][nt][1]);
            float2 v1 = make_float2(acc[mt][nt][2], acc[mt][nt][3]);
            if (BIAS) {
                float2 bb = *reinterpret_cast<const float2*>(&bias[c]);
                v0.x += bb.x; v0.y += bb.y;
                v1.x += bb.x; v1.y += bb.y;
            }
            *reinterpret_cast<float2*>(&C[r0 * ldc + c])       = v0;
            *reinterpret_cast<float2*>(&C[(r0 + 8) * ldc + c]) = v1;
        }
    }
}

// ---------------------------------------------------------------------------
// Row softmax, in place. One block (256 threads) per row of 2048 fp32.
// ---------------------------------------------------------------------------
__global__ __launch_bounds__(256)
void softmax2048(float* __restrict__ S)
{
    float* p = S + (long)blockIdx.x * 2048;
    const int tid = threadIdx.x;

    float4 v0 = reinterpret_cast<float4*>(p)[tid];
    float4 v1 = reinterpret_cast<float4*>(p)[tid + 256];

    float mx = fmaxf(fmaxf(fmaxf(v0.x, v0.y), fmaxf(v0.z, v0.w)),
                     fmaxf(fmaxf(v1.x, v1.y), fmaxf(v1.z, v1.w)));

    __shared__ float red[8];
#pragma unroll
    for (int o = 16; o > 0; o >>= 1) mx = fmaxf(mx, __shfl_xor_sync(0xffffffffu, mx, o));
    if ((tid & 31) == 0) red[tid >> 5] = mx;
    __syncthreads();
    if (tid == 0) {
        float m = red[0];
#pragma unroll
        for (int w = 1; w < 8; ++w) m = fmaxf(m, red[w]);
        red[0] = m;
    }
    __syncthreads();
    mx = red[0];
    __syncthreads();

    v0.x = __expf(v0.x - mx); v0.y = __expf(v0.y - mx);
    v0.z = __expf(v0.z - mx); v0.w = __expf(v0.w - mx);
    v1.x = __expf(v1.x - mx); v1.y = __expf(v1.y - mx);
    v1.z = __expf(v1.z - mx); v1.w = __expf(v1.w - mx);

    float s = (v0.x + v0.y + v0.z + v0.w) + (v1.x + v1.y + v1.z + v1.w);
#pragma unroll
    for (int o = 16; o > 0; o >>= 1) s += __shfl_xor_sync(0xffffffffu, s, o);
    if ((tid & 31) == 0) red[tid >> 5] = s;
    __syncthreads();
    if (tid == 0) {
        float t = 0.f;
#pragma unroll
        for (int w = 0; w < 8; ++w) t += red[w];
        red[0] = t;
    }
    __syncthreads();
    const float inv = 1.0f / red[0];

    v0.x *= inv; v0.y *= inv; v0.z *= inv; v0.w *= inv;
    v1.x *= inv; v1.y *= inv; v1.z *= inv; v1.w *= inv;
    reinterpret_cast<float4*>(p)[tid]       = v0;
    reinterpret_cast<float4*>(p)[tid + 256] = v1;
}

// ---------------------------------------------------------------------------
// Launch
// ---------------------------------------------------------------------------
extern "C" void kernel_launch(void* const* d_in, const int* in_sizes, int n_in,
                              void* d_out, int out_size)
{
    const float* Vf = (const float*)d_in[0];
    const float* Lf = (const float*)d_in[1];
    const float* Wv = (const float*)d_in[2];
    const float* bv = (const float*)d_in[3];
    const float* Wl = (const float*)d_in[4];
    const float* bl = (const float*)d_in[5];
    const float* Wo = (const float*)d_in[6];
    const float* bo = (const float*)d_in[7];
    float* out = (float*)d_out;

    float *vp, *lp, *sim, *comb;
    cudaGetSymbolAddress((void**)&vp,   g_vp);
    cudaGetSymbolAddress((void**)&lp,   g_lp);
    cudaGetSymbolAddress((void**)&sim,  g_sim);
    cudaGetSymbolAddress((void**)&comb, g_comb);

    const size_t SMEM = SMEM_B;   // 122880
    cudaFuncSetAttribute(tgemm<false, false, true >, cudaFuncAttributeMaxDynamicSharedMemorySize, SMEM);
    cudaFuncSetAttribute(tgemm<false, false, false>, cudaFuncAttributeMaxDynamicSharedMemorySize, SMEM);
    cudaFuncSetAttribute(tgemm<false, true,  false>, cudaFuncAttributeMaxDynamicSharedMemorySize, SMEM);
    cudaFuncSetAttribute(tgemm<true,  true,  false>, cudaFuncAttributeMaxDynamicSharedMemorySize, SMEM);

    const dim3 blk(256);
    const long sS = (long)SEQ * SEQ;     // sim batch stride
    const long sF = (long)SEQ * DIM;     // feature batch stride
    const long sO = (long)SEQ * 2 * DIM; // comb batch stride

    // vp = Vf @ Wv^T + bv   [16384,768]
    tgemm<false, false, true><<<dim3(DIM/128, TOK/128, 1), blk, SMEM>>>(
        Vf, DIM, 0, Wv, DIM, 0, vp, DIM, 0, DIM, bv);
    // lp = Lf @ Wl^T + bl
    tgemm<false, false, true><<<dim3(DIM/128, TOK/128, 1), blk, SMEM>>>(
        Lf, DIM, 0, Wl, DIM, 0, lp, DIM, 0, DIM, bl);
    // sim[b] = vp_b @ lp_b^T   [8,2048,2048]
    tgemm<false, false, false><<<dim3(SEQ/128, SEQ/128, BATCH), blk, SMEM>>>(
        vp, DIM, sF, lp, DIM, sF, sim, SEQ, sS, DIM, nullptr);
    // attn = softmax(sim) in place
    softmax2048<<<TOK, blk>>>(sim);
    // comb[:, :768] = av[b] = attn_b @ vp_b   (opB[n,k]=vp[k*DIM+n] -> TB)
    tgemm<false, true, false><<<dim3(DIM/128, SEQ/128, BATCH), blk, SMEM>>>(
        sim, SEQ, sS, vp, DIM, sF, comb, 2 * DIM, sO, SEQ, nullptr);
    // comb[:, 768:] = al[b] = attn_b^T @ lp_b (TA; opB[n,k]=lp[k*DIM+n] -> TB)
    tgemm<true, true, false><<<dim3(DIM/128, SEQ/128, BATCH), blk, SMEM>>>(
        sim, SEQ, sS, lp, DIM, sF, comb + DIM, 2 * DIM, sO, SEQ, nullptr);
    // out = comb @ Wo^T + bo   (K=1536)
    tgemm<false, false, true><<<dim3(DIM/128, TOK/128, 1), blk, SMEM>>>(
        comb, 2 * DIM, 0, Wo, 2 * DIM, 0, out, DIM, 0, 2 * DIM, bo);
}

// round 5
// speedup vs baseline: 2.6694x; 1.2535x over previous
#include <cuda_runtime.h>
#include <cuda_fp16.h>
#include <cstdint>

// ---------------------------------------------------------------------------
// B=8, L=2048, D=768.  Precision-tiered fp16 mma.sync GEMMs + fp32 softmax.
//   proj/sim/out : 3xFP16 (hi/lo split, err ~2^-22)
//   av/al        : 1xFP16 (attn in [0,1], no summation amplification)
// ---------------------------------------------------------------------------
#define BATCH 8
#define SEQ   2048
#define DIM   768
#define TOK   (BATCH * SEQ)          // 16384

// Scratch (device globals: allocation-free rule)
__device__ float g_vp [TOK * DIM];                 // [16384,768]
__device__ float g_lp [TOK * DIM];                 // [16384,768]
__device__ float g_sim[(long)BATCH * SEQ * SEQ];   // [8,2048,2048] -> attn in place
__device__ float g_comb[(long)TOK * 2 * DIM];      // [16384,1536]  av | al

// ---------------------------------------------------------------------------
// helpers
// ---------------------------------------------------------------------------
__device__ __forceinline__ void mma16(float* d, const uint32_t* a, const uint32_t* b) {
    asm volatile(
        "mma.sync.aligned.m16n8k16.row.col.f32.f16.f16.f32 "
        "{%0,%1,%2,%3}, {%4,%5,%6,%7}, {%8,%9}, {%0,%1,%2,%3};"
        : "+f"(d[0]), "+f"(d[1]), "+f"(d[2]), "+f"(d[3])
        : "r"(a[0]), "r"(a[1]), "r"(a[2]), "r"(a[3]), "r"(b[0]), "r"(b[1]));
}
__device__ __forceinline__ uint32_t lds_u32(const __half* p) {
    return *reinterpret_cast<const uint32_t*>(p);
}
// fp32 -> hi fp16 + lo fp16 (hi+lo captures ~22 mantissa bits)
__device__ __forceinline__ void split_h(float a, __half& h, __half& l) {
    h = __float2half_rn(a);
    l = __float2half_rn(a - __half2float(h));
}

// SMEM half-tile geometry: 128 rows x 32 k, row stride 40 halves (80 B)
#define ROWH    40
#define TILE_H  (128 * ROWH)          // halves per (hi or lo) tile
#define STAGE_H (4 * TILE_H)          // Ahi|Alo|Bhi|Blo
#define NSTAGE  3
#define SMEM_B  (NSTAGE * STAGE_H * 2) // bytes = 122880

// ---------------------------------------------------------------------------
// Stage LDG into registers (16 floats/thread):
//   TR=false: G[(row0+r)*ld + k0+k]   (float4)
//   TR=true : G[(k0+k)*ld + row0+m]   (coalesced scalar)
// ---------------------------------------------------------------------------
template<bool TR>
__device__ __forceinline__ void ldg_tile(const float* __restrict__ G, int ld,
                                         long row0, int k0, int tid, float* v)
{
    if (!TR) {
#pragma unroll
        for (int p = 0; p < 4; ++p) {
            const int idx = tid + p * 256;
            const int r   = idx >> 3;
            const int c4  = (idx & 7) * 4;
            float4 t = *reinterpret_cast<const float4*>(&G[(row0 + r) * (long)ld + k0 + c4]);
            v[p * 4 + 0] = t.x; v[p * 4 + 1] = t.y;
            v[p * 4 + 2] = t.z; v[p * 4 + 3] = t.w;
        }
    } else {
        const int m = tid & 127;
#pragma unroll
        for (int p = 0; p < 4; ++p) {
            const int kg = ((tid + p * 256) >> 7) * 4;
#pragma unroll
            for (int j = 0; j < 4; ++j)
                v[p * 4 + j] = G[(long)(k0 + kg + j) * ld + row0 + m];
        }
    }
}

// Split (optionally) + store registers into hi(/lo) SMEM tiles.
template<bool TR, bool SPLIT>
__device__ __forceinline__ void sts_tile(const float* v, __half* Shi, __half* Slo, int tid)
{
#pragma unroll
    for (int p = 0; p < 4; ++p) {
        __half h[4], l[4];
        if (SPLIT) {
#pragma unroll
            for (int j = 0; j < 4; ++j) split_h(v[p * 4 + j], h[j], l[j]);
        } else {
#pragma unroll
            for (int j = 0; j < 4; ++j) h[j] = __float2half_rn(v[p * 4 + j]);
        }
        int r, c;
        if (!TR) {
            const int idx = tid + p * 256;
            r = idx >> 3; c = (idx & 7) * 4;
        } else {
            r = tid & 127; c = ((tid + p * 256) >> 7) * 4;
        }
        *reinterpret_cast<__half2*>(&Shi[r * ROWH + c])     = __halves2half2(h[0], h[1]);
        *reinterpret_cast<__half2*>(&Shi[r * ROWH + c + 2]) = __halves2half2(h[2], h[3]);
        if (SPLIT) {
            *reinterpret_cast<__half2*>(&Slo[r * ROWH + c])     = __halves2half2(l[0], l[1]);
            *reinterpret_cast<__half2*>(&Slo[r * ROWH + c + 2]) = __halves2half2(l[2], l[3]);
        }
    }
}

// ---------------------------------------------------------------------------
// Precision-tiered GEMM via mma.sync m16n8k16, CTA tile 128x128, K-chunk 32,
// 3-buffer register-staged pipeline.
//   C[m,n] = sum_k opA[m,k]*opB[n,k] (+ bias[n])
//   SA/SB: hi/lo-split operand (3 or 2 or 1 MMAs per fragment)
// ---------------------------------------------------------------------------
template<bool TA, bool TB, bool SA, bool SB, bool BIAS>
__global__ __launch_bounds__(256)
void tgemm(const float* __restrict__ A, int lda, long sA,
           const float* __restrict__ B, int ldb, long sB,
           float* __restrict__ C, int ldc, long sC,
           int K, const float* __restrict__ bias)
{
    extern __shared__ __half hsm[];

    A += (long)blockIdx.z * sA;
    B += (long)blockIdx.z * sB;
    C += (long)blockIdx.z * sC;

    const int tid  = threadIdx.x;
    const int lane = tid & 31;
    const int wid  = tid >> 5;
    const int wm   = wid & 3;          // 4 warps along M
    const int wn   = wid >> 2;         // 2 warps along N
    const long m0  = (long)blockIdx.y * 128;
    const long n0  = (long)blockIdx.x * 128;
    const int lr   = lane >> 2;        // 0..7
    const int lc   = lane & 3;         // 0..3

    float acc[2][8][4];
#pragma unroll
    for (int i = 0; i < 2; ++i)
#pragma unroll
        for (int j = 0; j < 8; ++j)
#pragma unroll
            for (int q = 0; q < 4; ++q) acc[i][j][q] = 0.f;

    const int NIT = K / 32;
    float ra[16], rb[16];

    // prologue: stage 0 into smem buf0, stage 1 into registers
    ldg_tile<TA>(A, lda, m0, 0, tid, ra);
    ldg_tile<TB>(B, ldb, n0, 0, tid, rb);
    sts_tile<TA, SA>(ra, hsm,              hsm + TILE_H,     tid);
    sts_tile<TB, SB>(rb, hsm + 2 * TILE_H, hsm + 3 * TILE_H, tid);
    if (NIT > 1) {
        ldg_tile<TA>(A, lda, m0, 32, tid, ra);
        ldg_tile<TB>(B, ldb, n0, 32, tid, rb);
    }

    for (int it = 0; it < NIT; ++it) {
        __syncthreads();   // buf[it%3] stores visible; compute(it-1) done

        if (it + 1 < NIT) {
            __half* st = hsm + ((it + 1) % 3) * STAGE_H;
            sts_tile<TA, SA>(ra, st,              st + TILE_H,     tid);
            sts_tile<TB, SB>(rb, st + 2 * TILE_H, st + 3 * TILE_H, tid);
        }
        if (it + 2 < NIT) {
            ldg_tile<TA>(A, lda, m0, (it + 2) * 32, tid, ra);
            ldg_tile<TB>(B, ldb, n0, (it + 2) * 32, tid, rb);
        }

        const __half* Ahi = hsm + (it % 3) * STAGE_H;
        const __half* Alo = Ahi + TILE_H;
        const __half* Bhi = Ahi + 2 * TILE_H;
        const __half* Blo = Ahi + 3 * TILE_H;

#pragma unroll
        for (int ks = 0; ks < 2; ++ks) {
            const int kb = ks * 16;
            uint32_t ah[2][4], alr[2][4];
#pragma unroll
            for (int mt = 0; mt < 2; ++mt) {
                const int mb = wm * 32 + mt * 16;
                const int o0 = (mb + lr)     * ROWH + kb + 2 * lc;
                const int o1 = (mb + 8 + lr) * ROWH + kb + 2 * lc;
                ah[mt][0] = lds_u32(&Ahi[o0]);
                ah[mt][1] = lds_u32(&Ahi[o1]);
                ah[mt][2] = lds_u32(&Ahi[o0 + 8]);
                ah[mt][3] = lds_u32(&Ahi[o1 + 8]);
                if (SA) {
                    alr[mt][0] = lds_u32(&Alo[o0]);
                    alr[mt][1] = lds_u32(&Alo[o1]);
                    alr[mt][2] = lds_u32(&Alo[o0 + 8]);
                    alr[mt][3] = lds_u32(&Alo[o1 + 8]);
                }
            }
#pragma unroll
            for (int nt = 0; nt < 8; ++nt) {
                const int nb = wn * 64 + nt * 8;
                const int ob = (nb + lr) * ROWH + kb + 2 * lc;
                uint32_t bh[2], bl[2];
                bh[0] = lds_u32(&Bhi[ob]);
                bh[1] = lds_u32(&Bhi[ob + 8]);
                if (SB) {
                    bl[0] = lds_u32(&Blo[ob]);
                    bl[1] = lds_u32(&Blo[ob + 8]);
                }
#pragma unroll
                for (int mt = 0; mt < 2; ++mt) {
                    mma16(acc[mt][nt], ah[mt], bh);
                    if (SB) mma16(acc[mt][nt], ah[mt], bl);
                    if (SA) mma16(acc[mt][nt], alr[mt], bh);
                }
            }
        }
    }

    // ---- epilogue ----
#pragma unroll
    for (int mt = 0; mt < 2; ++mt) {
        const long r0 = m0 + wm * 32 + mt * 16 + lr;
#pragma unroll
        for (int nt = 0; nt < 8; ++nt) {
            const long c = n0 + wn * 64 + nt * 8 + lc * 2;
            float2 v0 = make_float2(acc[mt][nt][0], acc[mt][nt][1]);
            float2 v1 = make_float2(acc[mt][nt][2], acc[mt][nt][3]);
            if (BIAS) {
                float2 bb = *reinterpret_cast<const float2*>(&bias[c]);
                v0.x += bb.x; v0.y += bb.y;
                v1.x += bb.x; v1.y += bb.y;
            }
            *reinterpret_cast<float2*>(&C[r0 * ldc + c])       = v0;
            *reinterpret_cast<float2*>(&C[(r0 + 8) * ldc + c]) = v1;
        }
    }
}

// ---------------------------------------------------------------------------
// Row softmax, in place. One block (256 threads) per row of 2048 fp32.
// ---------------------------------------------------------------------------
__global__ __launch_bounds__(256)
void softmax2048(float* __restrict__ S)
{
    float* p = S + (long)blockIdx.x * 2048;
    const int tid = threadIdx.x;

    float4 v0 = reinterpret_cast<float4*>(p)[tid];
    float4 v1 = reinterpret_cast<float4*>(p)[tid + 256];

    float mx = fmaxf(fmaxf(fmaxf(v0.x, v0.y), fmaxf(v0.z, v0.w)),
                     fmaxf(fmaxf(v1.x, v1.y), fmaxf(v1.z, v1.w)));

    __shared__ float red[8];
#pragma unroll
    for (int o = 16; o > 0; o >>= 1) mx = fmaxf(mx, __shfl_xor_sync(0xffffffffu, mx, o));
    if ((tid & 31) == 0) red[tid >> 5] = mx;
    __syncthreads();
    if (tid == 0) {
        float m = red[0];
#pragma unroll
        for (int w = 1; w < 8; ++w) m = fmaxf(m, red[w]);
        red[0] = m;
    }
    __syncthreads();
    mx = red[0];
    __syncthreads();

    v0.x = __expf(v0.x - mx); v0.y = __expf(v0.y - mx);
    v0.z = __expf(v0.z - mx); v0.w = __expf(v0.w - mx);
    v1.x = __expf(v1.x - mx); v1.y = __expf(v1.y - mx);
    v1.z = __expf(v1.z - mx); v1.w = __expf(v1.w - mx);

    float s = (v0.x + v0.y + v0.z + v0.w) + (v1.x + v1.y + v1.z + v1.w);
#pragma unroll
    for (int o = 16; o > 0; o >>= 1) s += __shfl_xor_sync(0xffffffffu, s, o);
    if ((tid & 31) == 0) red[tid >> 5] = s;
    __syncthreads();
    if (tid == 0) {
        float t = 0.f;
#pragma unroll
        for (int w = 0; w < 8; ++w) t += red[w];
        red[0] = t;
    }
    __syncthreads();
    const float inv = 1.0f / red[0];

    v0.x *= inv; v0.y *= inv; v0.z *= inv; v0.w *= inv;
    v1.x *= inv; v1.y *= inv; v1.z *= inv; v1.w *= inv;
    reinterpret_cast<float4*>(p)[tid]       = v0;
    reinterpret_cast<float4*>(p)[tid + 256] = v1;
}

// ---------------------------------------------------------------------------
// Launch
// ---------------------------------------------------------------------------
extern "C" void kernel_launch(void* const* d_in, const int* in_sizes, int n_in,
                              void* d_out, int out_size)
{
    const float* Vf = (const float*)d_in[0];
    const float* Lf = (const float*)d_in[1];
    const float* Wv = (const float*)d_in[2];
    const float* bv = (const float*)d_in[3];
    const float* Wl = (const float*)d_in[4];
    const float* bl = (const float*)d_in[5];
    const float* Wo = (const float*)d_in[6];
    const float* bo = (const float*)d_in[7];
    float* out = (float*)d_out;

    float *vp, *lp, *sim, *comb;
    cudaGetSymbolAddress((void**)&vp,   g_vp);
    cudaGetSymbolAddress((void**)&lp,   g_lp);
    cudaGetSymbolAddress((void**)&sim,  g_sim);
    cudaGetSymbolAddress((void**)&comb, g_comb);

    const size_t SMEM = SMEM_B;   // 122880
    cudaFuncSetAttribute(tgemm<false, false, true,  true,  true >, cudaFuncAttributeMaxDynamicSharedMemorySize, SMEM);
    cudaFuncSetAttribute(tgemm<false, false, true,  true,  false>, cudaFuncAttributeMaxDynamicSharedMemorySize, SMEM);
    cudaFuncSetAttribute(tgemm<false, true,  false, false, false>, cudaFuncAttributeMaxDynamicSharedMemorySize, SMEM);
    cudaFuncSetAttribute(tgemm<true,  true,  false, false, false>, cudaFuncAttributeMaxDynamicSharedMemorySize, SMEM);

    const dim3 blk(256);
    const long sS = (long)SEQ * SEQ;     // sim batch stride
    const long sF = (long)SEQ * DIM;     // feature batch stride
    const long sO = (long)SEQ * 2 * DIM; // comb batch stride

    // vp = Vf @ Wv^T + bv   [16384,768]   (3x)
    tgemm<false, false, true, true, true><<<dim3(DIM/128, TOK/128, 1), blk, SMEM>>>(
        Vf, DIM, 0, Wv, DIM, 0, vp, DIM, 0, DIM, bv);
    // lp = Lf @ Wl^T + bl   (3x)
    tgemm<false, false, true, true, true><<<dim3(DIM/128, TOK/128, 1), blk, SMEM>>>(
        Lf, DIM, 0, Wl, DIM, 0, lp, DIM, 0, DIM, bl);
    // sim[b] = vp_b @ lp_b^T   [8,2048,2048]   (3x)
    tgemm<false, false, true, true, false><<<dim3(SEQ/128, SEQ/128, BATCH), blk, SMEM>>>(
        vp, DIM, sF, lp, DIM, sF, sim, SEQ, sS, DIM, nullptr);
    // attn = softmax(sim) in place
    softmax2048<<<TOK, blk>>>(sim);
    // comb[:, :768] = av[b] = attn_b @ vp_b   (1x: attn in [0,1], vp direct)
    tgemm<false, true, false, false, false><<<dim3(DIM/128, SEQ/128, BATCH), blk, SMEM>>>(
        sim, SEQ, sS, vp, DIM, sF, comb, 2 * DIM, sO, SEQ, nullptr);
    // comb[:, 768:] = al[b] = attn_b^T @ lp_b   (1x)
    tgemm<true, true, false, false, false><<<dim3(DIM/128, SEQ/128, BATCH), blk, SMEM>>>(
        sim, SEQ, sS, lp, DIM, sF, comb + DIM, 2 * DIM, sO, SEQ, nullptr);
    // out = comb @ Wo^T + bo   (K=1536, 3x)
    tgemm<false, false, true, true, true><<<dim3(DIM/128, TOK/128, 1), blk, SMEM>>>(
        comb, 2 * DIM, 0, Wo, 2 * DIM, 0, out, DIM, 0, 2 * DIM, bo);
}

// round 6
// speedup vs baseline: 2.9812x; 1.1168x over previous
#include <cuda_runtime.h>
#include <cuda_fp16.h>
#include <cstdint>

// ---------------------------------------------------------------------------
// B=8, L=2048, D=768.  Precision-tiered fp16 mma.sync GEMMs + fp32 softmax.
//   proj/sim : 3xFP16 (hi/lo split both operands, err ~2^-22)
//   out      : 2xFP16 (split comb only; Wo single fp16)
//   av/al    : 1xFP16 (attn in [0,1], no summation amplification)
// Launch merging: proj pair in one launch, av+al in one launch (tail waves).
// ---------------------------------------------------------------------------
#define BATCH 8
#define SEQ   2048
#define DIM   768
#define TOK   (BATCH * SEQ)          // 16384

// Scratch (device globals: allocation-free rule)
__device__ float g_vp [TOK * DIM];                 // [16384,768]
__device__ float g_lp [TOK * DIM];                 // [16384,768]
__device__ float g_sim[(long)BATCH * SEQ * SEQ];   // [8,2048,2048] -> attn in place
__device__ float g_comb[(long)TOK * 2 * DIM];      // [16384,1536]  av | al

// ---------------------------------------------------------------------------
// helpers
// ---------------------------------------------------------------------------
__device__ __forceinline__ void mma16(float* d, const uint32_t* a, const uint32_t* b) {
    asm volatile(
        "mma.sync.aligned.m16n8k16.row.col.f32.f16.f16.f32 "
        "{%0,%1,%2,%3}, {%4,%5,%6,%7}, {%8,%9}, {%0,%1,%2,%3};"
        : "+f"(d[0]), "+f"(d[1]), "+f"(d[2]), "+f"(d[3])
        : "r"(a[0]), "r"(a[1]), "r"(a[2]), "r"(a[3]), "r"(b[0]), "r"(b[1]));
}
__device__ __forceinline__ uint32_t lds_u32(const __half* p) {
    return *reinterpret_cast<const uint32_t*>(p);
}
// fp32 -> hi fp16 + lo fp16 (hi+lo captures ~22 mantissa bits)
__device__ __forceinline__ void split_h(float a, __half& h, __half& l) {
    h = __float2half_rn(a);
    l = __float2half_rn(a - __half2float(h));
}

// SMEM half-tile geometry: 128 rows x 32 k, row stride 40 halves (80 B)
#define ROWH    40
#define TILE_H  (128 * ROWH)          // halves per (hi or lo) tile
#define STAGE_H (4 * TILE_H)          // Ahi|Alo|Bhi|Blo
#define NSTAGE  3
#define SMEM_B  (NSTAGE * STAGE_H * 2) // bytes = 122880

// ---------------------------------------------------------------------------
// Stage LDG into registers (16 floats/thread):
//   TR=false: G[(row0+r)*ld + k0+k]   (float4)
//   TR=true : G[(k0+k)*ld + row0+m]   (coalesced scalar)
// ---------------------------------------------------------------------------
template<bool TR>
__device__ __forceinline__ void ldg_tile(const float* __restrict__ G, int ld,
                                         long row0, int k0, int tid, float* v)
{
    if (!TR) {
#pragma unroll
        for (int p = 0; p < 4; ++p) {
            const int idx = tid + p * 256;
            const int r   = idx >> 3;
            const int c4  = (idx & 7) * 4;
            float4 t = *reinterpret_cast<const float4*>(&G[(row0 + r) * (long)ld + k0 + c4]);
            v[p * 4 + 0] = t.x; v[p * 4 + 1] = t.y;
            v[p * 4 + 2] = t.z; v[p * 4 + 3] = t.w;
        }
    } else {
        const int m = tid & 127;
#pragma unroll
        for (int p = 0; p < 4; ++p) {
            const int kg = ((tid + p * 256) >> 7) * 4;
#pragma unroll
            for (int j = 0; j < 4; ++j)
                v[p * 4 + j] = G[(long)(k0 + kg + j) * ld + row0 + m];
        }
    }
}

// Split (optionally) + store registers into hi(/lo) SMEM tiles.
template<bool TR, bool SPLIT>
__device__ __forceinline__ void sts_tile(const float* v, __half* Shi, __half* Slo, int tid)
{
#pragma unroll
    for (int p = 0; p < 4; ++p) {
        __half h[4], l[4];
        if (SPLIT) {
#pragma unroll
            for (int j = 0; j < 4; ++j) split_h(v[p * 4 + j], h[j], l[j]);
        } else {
#pragma unroll
            for (int j = 0; j < 4; ++j) h[j] = __float2half_rn(v[p * 4 + j]);
        }
        int r, c;
        if (!TR) {
            const int idx = tid + p * 256;
            r = idx >> 3; c = (idx & 7) * 4;
        } else {
            r = tid & 127; c = ((tid + p * 256) >> 7) * 4;
        }
        *reinterpret_cast<__half2*>(&Shi[r * ROWH + c])     = __halves2half2(h[0], h[1]);
        *reinterpret_cast<__half2*>(&Shi[r * ROWH + c + 2]) = __halves2half2(h[2], h[3]);
        if (SPLIT) {
            *reinterpret_cast<__half2*>(&Slo[r * ROWH + c])     = __halves2half2(l[0], l[1]);
            *reinterpret_cast<__half2*>(&Slo[r * ROWH + c + 2]) = __halves2half2(l[2], l[3]);
        }
    }
}

// ---------------------------------------------------------------------------
// GEMM body: mma.sync m16n8k16, CTA tile 128x128, K-chunk 32,
// 3-buffer register-staged pipeline.
//   C[m,n] = sum_k opA[m,k]*opB[n,k] (+ bias[n])
//   SA/SB: hi/lo-split operand
// ---------------------------------------------------------------------------
template<bool TA, bool TB, bool SA, bool SB, bool BIAS>
__device__ __forceinline__ void gemm_body(
    const float* __restrict__ A, int lda,
    const float* __restrict__ B, int ldb,
    float* __restrict__ C, int ldc,
    int K, const float* __restrict__ bias, __half* hsm)
{
    const int tid  = threadIdx.x;
    const int lane = tid & 31;
    const int wid  = tid >> 5;
    const int wm   = wid & 3;          // 4 warps along M
    const int wn   = wid >> 2;         // 2 warps along N
    const long m0  = (long)blockIdx.y * 128;
    const long n0  = (long)blockIdx.x * 128;
    const int lr   = lane >> 2;        // 0..7
    const int lc   = lane & 3;         // 0..3

    float acc[2][8][4];
#pragma unroll
    for (int i = 0; i < 2; ++i)
#pragma unroll
        for (int j = 0; j < 8; ++j)
#pragma unroll
            for (int q = 0; q < 4; ++q) acc[i][j][q] = 0.f;

    const int NIT = K / 32;
    float ra[16], rb[16];

    // prologue: stage 0 into smem buf0, stage 1 into registers
    ldg_tile<TA>(A, lda, m0, 0, tid, ra);
    ldg_tile<TB>(B, ldb, n0, 0, tid, rb);
    sts_tile<TA, SA>(ra, hsm,              hsm + TILE_H,     tid);
    sts_tile<TB, SB>(rb, hsm + 2 * TILE_H, hsm + 3 * TILE_H, tid);
    if (NIT > 1) {
        ldg_tile<TA>(A, lda, m0, 32, tid, ra);
        ldg_tile<TB>(B, ldb, n0, 32, tid, rb);
    }

    for (int it = 0; it < NIT; ++it) {
        __syncthreads();   // buf[it%3] stores visible; compute(it-1) done

        if (it + 1 < NIT) {
            __half* st = hsm + ((it + 1) % 3) * STAGE_H;
            sts_tile<TA, SA>(ra, st,              st + TILE_H,     tid);
            sts_tile<TB, SB>(rb, st + 2 * TILE_H, st + 3 * TILE_H, tid);
        }
        if (it + 2 < NIT) {
            ldg_tile<TA>(A, lda, m0, (it + 2) * 32, tid, ra);
            ldg_tile<TB>(B, ldb, n0, (it + 2) * 32, tid, rb);
        }

        const __half* Ahi = hsm + (it % 3) * STAGE_H;
        const __half* Alo = Ahi + TILE_H;
        const __half* Bhi = Ahi + 2 * TILE_H;
        const __half* Blo = Ahi + 3 * TILE_H;

#pragma unroll
        for (int ks = 0; ks < 2; ++ks) {
            const int kb = ks * 16;
            uint32_t ah[2][4], alr[2][4];
#pragma unroll
            for (int mt = 0; mt < 2; ++mt) {
                const int mb = wm * 32 + mt * 16;
                const int o0 = (mb + lr)     * ROWH + kb + 2 * lc;
                const int o1 = (mb + 8 + lr) * ROWH + kb + 2 * lc;
                ah[mt][0] = lds_u32(&Ahi[o0]);
                ah[mt][1] = lds_u32(&Ahi[o1]);
                ah[mt][2] = lds_u32(&Ahi[o0 + 8]);
                ah[mt][3] = lds_u32(&Ahi[o1 + 8]);
                if (SA) {
                    alr[mt][0] = lds_u32(&Alo[o0]);
                    alr[mt][1] = lds_u32(&Alo[o1]);
                    alr[mt][2] = lds_u32(&Alo[o0 + 8]);
                    alr[mt][3] = lds_u32(&Alo[o1 + 8]);
                }
            }
#pragma unroll
            for (int nt = 0; nt < 8; ++nt) {
                const int nb = wn * 64 + nt * 8;
                const int ob = (nb + lr) * ROWH + kb + 2 * lc;
                uint32_t bh[2], bl[2];
                bh[0] = lds_u32(&Bhi[ob]);
                bh[1] = lds_u32(&Bhi[ob + 8]);
                if (SB) {
                    bl[0] = lds_u32(&Blo[ob]);
                    bl[1] = lds_u32(&Blo[ob + 8]);
                }
#pragma unroll
                for (int mt = 0; mt < 2; ++mt) {
                    mma16(acc[mt][nt], ah[mt], bh);
                    if (SB) mma16(acc[mt][nt], ah[mt], bl);
                    if (SA) mma16(acc[mt][nt], alr[mt], bh);
                }
            }
        }
    }

    // ---- epilogue ----
#pragma unroll
    for (int mt = 0; mt < 2; ++mt) {
        const long r0 = m0 + wm * 32 + mt * 16 + lr;
#pragma unroll
        for (int nt = 0; nt < 8; ++nt) {
            const long c = n0 + wn * 64 + nt * 8 + lc * 2;
            float2 v0 = make_float2(acc[mt][nt][0], acc[mt][nt][1]);
            float2 v1 = make_float2(acc[mt][nt][2], acc[mt][nt][3]);
            if (BIAS) {
                float2 bb = *reinterpret_cast<const float2*>(&bias[c]);
                v0.x += bb.x; v0.y += bb.y;
                v1.x += bb.x; v1.y += bb.y;
            }
            *reinterpret_cast<float2*>(&C[r0 * ldc + c])       = v0;
            *reinterpret_cast<float2*>(&C[(r0 + 8) * ldc + c]) = v1;
        }
    }
}

// ---------------------------------------------------------------------------
// Kernels
// ---------------------------------------------------------------------------

// Batched GEMM wrapper (used for sim and out).
template<bool TA, bool TB, bool SA, bool SB, bool BIAS>
__global__ __launch_bounds__(256)
void tgemm(const float* __restrict__ A, int lda, long sA,
           const float* __restrict__ B, int ldb, long sB,
           float* __restrict__ C, int ldc, long sC,
           int K, const float* __restrict__ bias)
{
    extern __shared__ __half hsm[];
    gemm_body<TA, TB, SA, SB, BIAS>(
        A + (long)blockIdx.z * sA, lda,
        B + (long)blockIdx.z * sB, ldb,
        C + (long)blockIdx.z * sC, ldc, K, bias, hsm);
}

// Both projections in one launch: z=0 -> vp, z=1 -> lp.  3x, bias.
__global__ __launch_bounds__(256)
void proj_both(const float* __restrict__ Vf, const float* __restrict__ Lf,
               const float* __restrict__ Wv, const float* __restrict__ bv,
               const float* __restrict__ Wl, const float* __restrict__ bl,
               float* __restrict__ vp, float* __restrict__ lp)
{
    extern __shared__ __half hsm[];
    const int z = blockIdx.z;
    const float* A    = z ? Lf : Vf;
    const float* B    = z ? Wl : Wv;
    const float* bias = z ? bl : bv;
    float*       C    = z ? lp : vp;
    gemm_body<false, false, true, true, true>(A, DIM, B, DIM, C, DIM, DIM, bias, hsm);
}

// av and al in one launch: z in [0,16): b = z&7, mode = z>>3.
//   mode 0: comb[b][:, :768]  = attn_b   @ vp_b   (1x)
//   mode 1: comb[b][:, 768:]  = attn_b^T @ lp_b   (1x)
// Uniform per-CTA branch -> __syncthreads inside is safe.
__global__ __launch_bounds__(256)
void attn_av_al(const float* __restrict__ sim,
                const float* __restrict__ vp, const float* __restrict__ lp,
                float* __restrict__ comb)
{
    extern __shared__ __half hsm[];
    const int z    = blockIdx.z;
    const int b    = z & 7;
    const long sS  = (long)SEQ * SEQ;
    const long sF  = (long)SEQ * DIM;
    const long sO  = (long)SEQ * 2 * DIM;
    const float* Ab = sim + b * sS;
    if ((z >> 3) == 0) {
        gemm_body<false, true, false, false, false>(
            Ab, SEQ, vp + b * sF, DIM, comb + b * sO, 2 * DIM, SEQ, nullptr, hsm);
    } else {
        gemm_body<true, true, false, false, false>(
            Ab, SEQ, lp + b * sF, DIM, comb + b * sO + DIM, 2 * DIM, SEQ, nullptr, hsm);
    }
}

// ---------------------------------------------------------------------------
// Row softmax, in place. One block (256 threads) per row of 2048 fp32.
// ---------------------------------------------------------------------------
__global__ __launch_bounds__(256)
void softmax2048(float* __restrict__ S)
{
    float* p = S + (long)blockIdx.x * 2048;
    const int tid = threadIdx.x;

    float4 v0 = reinterpret_cast<float4*>(p)[tid];
    float4 v1 = reinterpret_cast<float4*>(p)[tid + 256];

    float mx = fmaxf(fmaxf(fmaxf(v0.x, v0.y), fmaxf(v0.z, v0.w)),
                     fmaxf(fmaxf(v1.x, v1.y), fmaxf(v1.z, v1.w)));

    __shared__ float red[8];
#pragma unroll
    for (int o = 16; o > 0; o >>= 1) mx = fmaxf(mx, __shfl_xor_sync(0xffffffffu, mx, o));
    if ((tid & 31) == 0) red[tid >> 5] = mx;
    __syncthreads();
    if (tid == 0) {
        float m = red[0];
#pragma unroll
        for (int w = 1; w < 8; ++w) m = fmaxf(m, red[w]);
        red[0] = m;
    }
    __syncthreads();
    mx = red[0];
    __syncthreads();

    v0.x = __expf(v0.x - mx); v0.y = __expf(v0.y - mx);
    v0.z = __expf(v0.z - mx); v0.w = __expf(v0.w - mx);
    v1.x = __expf(v1.x - mx); v1.y = __expf(v1.y - mx);
    v1.z = __expf(v1.z - mx); v1.w = __expf(v1.w - mx);

    float s = (v0.x + v0.y + v0.z + v0.w) + (v1.x + v1.y + v1.z + v1.w);
#pragma unroll
    for (int o = 16; o > 0; o >>= 1) s += __shfl_xor_sync(0xffffffffu, s, o);
    if ((tid & 31) == 0) red[tid >> 5] = s;
    __syncthreads();
    if (tid == 0) {
        float t = 0.f;
#pragma unroll
        for (int w = 0; w < 8; ++w) t += red[w];
        red[0] = t;
    }
    __syncthreads();
    const float inv = 1.0f / red[0];

    v0.x *= inv; v0.y *= inv; v0.z *= inv; v0.w *= inv;
    v1.x *= inv; v1.y *= inv; v1.z *= inv; v1.w *= inv;
    reinterpret_cast<float4*>(p)[tid]       = v0;
    reinterpret_cast<float4*>(p)[tid + 256] = v1;
}

// ---------------------------------------------------------------------------
// Launch
// ---------------------------------------------------------------------------
extern "C" void kernel_launch(void* const* d_in, const int* in_sizes, int n_in,
                              void* d_out, int out_size)
{
    const float* Vf = (const float*)d_in[0];
    const float* Lf = (const float*)d_in[1];
    const float* Wv = (const float*)d_in[2];
    const float* bv = (const float*)d_in[3];
    const float* Wl = (const float*)d_in[4];
    const float* bl = (const float*)d_in[5];
    const float* Wo = (const float*)d_in[6];
    const float* bo = (const float*)d_in[7];
    float* out = (float*)d_out;

    float *vp, *lp, *sim, *comb;
    cudaGetSymbolAddress((void**)&vp,   g_vp);
    cudaGetSymbolAddress((void**)&lp,   g_lp);
    cudaGetSymbolAddress((void**)&sim,  g_sim);
    cudaGetSymbolAddress((void**)&comb, g_comb);

    const size_t SMEM = SMEM_B;   // 122880
    cudaFuncSetAttribute(proj_both,  cudaFuncAttributeMaxDynamicSharedMemorySize, SMEM);
    cudaFuncSetAttribute(attn_av_al, cudaFuncAttributeMaxDynamicSharedMemorySize, SMEM);
    cudaFuncSetAttribute(tgemm<false, false, true, true,  false>, cudaFuncAttributeMaxDynamicSharedMemorySize, SMEM);
    cudaFuncSetAttribute(tgemm<false, false, true, false, true >, cudaFuncAttributeMaxDynamicSharedMemorySize, SMEM);

    const dim3 blk(256);
    const long sS = (long)SEQ * SEQ;     // sim batch stride
    const long sF = (long)SEQ * DIM;     // feature batch stride

    // vp/lp projections, one launch (3x, bias)
    proj_both<<<dim3(DIM/128, TOK/128, 2), blk, SMEM>>>(Vf, Lf, Wv, bv, Wl, bl, vp, lp);
    // sim[b] = vp_b @ lp_b^T   [8,2048,2048]   (3x)
    tgemm<false, false, true, true, false><<<dim3(SEQ/128, SEQ/128, BATCH), blk, SMEM>>>(
        vp, DIM, sF, lp, DIM, sF, sim, SEQ, sS, DIM, nullptr);
    // attn = softmax(sim) in place
    softmax2048<<<TOK, blk>>>(sim);
    // av + al, one launch (1x)
    attn_av_al<<<dim3(DIM/128, SEQ/128, 2 * BATCH), blk, SMEM>>>(sim, vp, lp, comb);
    // out = comb @ Wo^T + bo   (K=1536, 2x: comb split, Wo single)
    tgemm<false, false, true, false, true><<<dim3(DIM/128, TOK/128, 1), blk, SMEM>>>(
        comb, 2 * DIM, 0, Wo, 2 * DIM, 0, out, DIM, 0, 2 * DIM, bo);
}

// round 7
// speedup vs baseline: 3.1890x; 1.0697x over previous
#include <cuda_runtime.h>
#include <cuda_fp16.h>
#include <cstdint>

// ---------------------------------------------------------------------------
// B=8, L=2048, D=768.  fp16-in-gmem cp.async GEMMs, precision-tiered:
//   proj (fp32 in) : 3xFP16 register-staged; writes vp/lp as fp16 hi+lo
//   sim            : 3xFP16, all-fp16 cp.async
//   av/al          : 1xFP16, all-fp16 cp.async (transposed operands pre-built)
//   out            : 2xFP16 (comb hi/lo x Wo16), cp.async
// ---------------------------------------------------------------------------
#define BATCH 8
#define SEQ   2048
#define DIM   768
#define TOK   (BATCH * SEQ)          // 16384

// Scratch (device globals: allocation-free rule)
__device__ __half g_vph [TOK * DIM];                 // vp hi   [16384,768]
__device__ __half g_vpl [TOK * DIM];                 // vp lo
__device__ __half g_lph [TOK * DIM];                 // lp hi
__device__ __half g_lpl [TOK * DIM];                 // lp lo
__device__ __half g_vpt [TOK * DIM];                 // vp^T   [8][768][2048]
__device__ __half g_lpt [TOK * DIM];                 // lp^T   [8][768][2048]
__device__ float  g_sim [(long)BATCH * SEQ * SEQ];   // [8,2048,2048]
__device__ __half g_at  [(long)BATCH * SEQ * SEQ];   // attn   [8][2048][2048]
__device__ __half g_att [(long)BATCH * SEQ * SEQ];   // attn^T [8][2048][2048]
__device__ __half g_cbh [(long)TOK * 2 * DIM];       // comb hi [16384,1536]
__device__ __half g_cbl [(long)TOK * 2 * DIM];       // comb lo
__device__ __half g_wo16[DIM * 2 * DIM];             // Wo fp16 [768,1536]

// ---------------------------------------------------------------------------
// helpers
// ---------------------------------------------------------------------------
__device__ __forceinline__ uint32_t smem_u32(const void* p) {
    uint32_t a;
    asm("{ .reg .u64 t; cvta.to.shared.u64 t, %1; cvt.u32.u64 %0, t; }"
        : "=r"(a) : "l"(p));
    return a;
}
__device__ __forceinline__ void cp16(uint32_t s, const void* g) {
    asm volatile("cp.async.ca.shared.global [%0], [%1], 16;" :: "r"(s), "l"(g));
}
#define CP_COMMIT() asm volatile("cp.async.commit_group;" ::: "memory")
template<int N>
__device__ __forceinline__ void cp_wait() {
    asm volatile("cp.async.wait_group %0;" :: "n"(N) : "memory");
}
__device__ __forceinline__ void mma16(float* d, const uint32_t* a, const uint32_t* b) {
    asm volatile(
        "mma.sync.aligned.m16n8k16.row.col.f32.f16.f16.f32 "
        "{%0,%1,%2,%3}, {%4,%5,%6,%7}, {%8,%9}, {%0,%1,%2,%3};"
        : "+f"(d[0]), "+f"(d[1]), "+f"(d[2]), "+f"(d[3])
        : "r"(a[0]), "r"(a[1]), "r"(a[2]), "r"(a[3]), "r"(b[0]), "r"(b[1]));
}
__device__ __forceinline__ uint32_t lds_u32(const __half* p) {
    return *reinterpret_cast<const uint32_t*>(p);
}
__device__ __forceinline__ void split_h(float a, __half& h, __half& l) {
    h = __float2half_rn(a);
    l = __float2half_rn(a - __half2float(h));
}

// SMEM tile: 128 rows x 32 k halves, row stride 40 halves (80 B)
#define ROWH    40
#define TILE16  (128 * ROWH)          // halves per tile (10240 B)

// ---------------------------------------------------------------------------
// fp16 cp.async stage loader: 128 rows x 32 k from src[(row0+r)*ld + k0 + c]
// ---------------------------------------------------------------------------
__device__ __forceinline__ void load_stage16(__half* dst, const __half* __restrict__ src,
                                             int ld, long row0, int k0, int tid)
{
#pragma unroll
    for (int p = 0; p < 2; ++p) {
        const int idx = tid + p * 256;       // 0..511
        const int r   = idx >> 2;            // 0..127
        const int c8  = (idx & 3) * 8;       // 0,8,16,24
        cp16(smem_u32(&dst[r * ROWH + c8]), &src[(row0 + r) * (long)ld + k0 + c8]);
    }
}

// ---------------------------------------------------------------------------
// All-fp16 GEMM body: mma.sync m16n8k16, CTA tile 128x128, K-chunk 32,
// NST-stage cp.async pipeline.  C[m,n] = sum_k opA[m,k]*opB[n,k]
//   SA: A has hi+lo tiles; SB: B has hi+lo tiles (3x/2x/1x MMA per fragment)
//   WSPLIT: write split fp16 hi/lo C; else fp32 C (+bias if BIAS)
// ---------------------------------------------------------------------------
template<bool SA, bool SB, int NST, bool WSPLIT, bool BIAS>
__device__ __forceinline__ void gemm16_body(
    const __half* __restrict__ Ah, const __half* __restrict__ Al, int lda,
    const __half* __restrict__ Bh, const __half* __restrict__ Bl, int ldb,
    float* __restrict__ Cf, __half* __restrict__ Ch, __half* __restrict__ Cl, int ldc,
    int K, const float* __restrict__ bias, __half* hsm)
{
    constexpr int NTIL = (SA ? 2 : 1) + (SB ? 2 : 1);
    constexpr int STG  = NTIL * TILE16;

    const int tid  = threadIdx.x;
    const int lane = tid & 31;
    const int wid  = tid >> 5;
    const int wm   = wid & 3;
    const int wn   = wid >> 2;
    const long m0  = (long)blockIdx.y * 128;
    const long n0  = (long)blockIdx.x * 128;
    const int lr   = lane >> 2;
    const int lc   = lane & 3;

    float acc[2][8][4];
#pragma unroll
    for (int i = 0; i < 2; ++i)
#pragma unroll
        for (int j = 0; j < 8; ++j)
#pragma unroll
            for (int q = 0; q < 4; ++q) acc[i][j][q] = 0.f;

    const int NIT = K / 32;

    auto issue = [&](int st) {
        if (st < NIT) {
            __half* s = hsm + (st % NST) * STG;
            const int k0 = st * 32;
            load_stage16(s, Ah, lda, m0, k0, tid);
            if (SA) load_stage16(s + TILE16, Al, lda, m0, k0, tid);
            __half* sb = s + (SA ? 2 : 1) * TILE16;
            load_stage16(sb, Bh, ldb, n0, k0, tid);
            if (SB) load_stage16(sb + TILE16, Bl, ldb, n0, k0, tid);
        }
        CP_COMMIT();
    };

#pragma unroll
    for (int s = 0; s < NST - 1; ++s) issue(s);

    for (int it = 0; it < NIT; ++it) {
        cp_wait<NST - 2>();
        __syncthreads();
        issue(it + NST - 1);

        const __half* At = hsm + (it % NST) * STG;
        const __half* AtL = At + TILE16;
        const __half* Bt = At + (SA ? 2 : 1) * TILE16;
        const __half* BtL = Bt + TILE16;

#pragma unroll
        for (int ks = 0; ks < 2; ++ks) {
            const int kb = ks * 16;
            uint32_t ah[2][4], al[2][4];
#pragma unroll
            for (int mt = 0; mt < 2; ++mt) {
                const int mb = wm * 32 + mt * 16;
                const int o0 = (mb + lr)     * ROWH + kb + 2 * lc;
                const int o1 = (mb + 8 + lr) * ROWH + kb + 2 * lc;
                ah[mt][0] = lds_u32(&At[o0]);
                ah[mt][1] = lds_u32(&At[o1]);
                ah[mt][2] = lds_u32(&At[o0 + 8]);
                ah[mt][3] = lds_u32(&At[o1 + 8]);
                if (SA) {
                    al[mt][0] = lds_u32(&AtL[o0]);
                    al[mt][1] = lds_u32(&AtL[o1]);
                    al[mt][2] = lds_u32(&AtL[o0 + 8]);
                    al[mt][3] = lds_u32(&AtL[o1 + 8]);
                }
            }
#pragma unroll
            for (int nt = 0; nt < 8; ++nt) {
                const int nb = wn * 64 + nt * 8;
                const int ob = (nb + lr) * ROWH + kb + 2 * lc;
                uint32_t bh[2], bl[2];
                bh[0] = lds_u32(&Bt[ob]);
                bh[1] = lds_u32(&Bt[ob + 8]);
                if (SB) {
                    bl[0] = lds_u32(&BtL[ob]);
                    bl[1] = lds_u32(&BtL[ob + 8]);
                }
#pragma unroll
                for (int mt = 0; mt < 2; ++mt) {
                    mma16(acc[mt][nt], ah[mt], bh);
                    if (SB) mma16(acc[mt][nt], ah[mt], bl);
                    if (SA) mma16(acc[mt][nt], al[mt], bh);
                }
            }
        }
    }

    // ---- epilogue ----
#pragma unroll
    for (int mt = 0; mt < 2; ++mt) {
        const long r0 = m0 + wm * 32 + mt * 16 + lr;
#pragma unroll
        for (int nt = 0; nt < 8; ++nt) {
            const long c = n0 + wn * 64 + nt * 8 + lc * 2;
            float v[4] = {acc[mt][nt][0], acc[mt][nt][1], acc[mt][nt][2], acc[mt][nt][3]};
            if (BIAS) {
                float2 bb = *reinterpret_cast<const float2*>(&bias[c]);
                v[0] += bb.x; v[1] += bb.y; v[2] += bb.x; v[3] += bb.y;
            }
            if (WSPLIT) {
                __half h[4], l[4];
#pragma unroll
                for (int q = 0; q < 4; ++q) split_h(v[q], h[q], l[q]);
                *reinterpret_cast<__half2*>(&Ch[r0 * ldc + c])       = __halves2half2(h[0], h[1]);
                *reinterpret_cast<__half2*>(&Ch[(r0 + 8) * ldc + c]) = __halves2half2(h[2], h[3]);
                *reinterpret_cast<__half2*>(&Cl[r0 * ldc + c])       = __halves2half2(l[0], l[1]);
                *reinterpret_cast<__half2*>(&Cl[(r0 + 8) * ldc + c]) = __halves2half2(l[2], l[3]);
            } else {
                *reinterpret_cast<float2*>(&Cf[r0 * ldc + c])       = make_float2(v[0], v[1]);
                *reinterpret_cast<float2*>(&Cf[(r0 + 8) * ldc + c]) = make_float2(v[2], v[3]);
            }
        }
    }
}

// ---------------------------------------------------------------------------
// Projection kernel (fp32 inputs): 3x register-staged, writes fp16 hi/lo.
// ---------------------------------------------------------------------------
#define PROWH    40
#define PTILE_H  (128 * PROWH)
#define PSTAGE_H (4 * PTILE_H)
#define PNSTAGE  3
#define PSMEM_B  (PNSTAGE * PSTAGE_H * 2)   // 122880

__device__ __forceinline__ void p_ldg(const float* __restrict__ G, int ld,
                                      long row0, int k0, int tid, float* v)
{
#pragma unroll
    for (int p = 0; p < 4; ++p) {
        const int idx = tid + p * 256;
        const int r   = idx >> 3;
        const int c4  = (idx & 7) * 4;
        float4 t = *reinterpret_cast<const float4*>(&G[(row0 + r) * (long)ld + k0 + c4]);
        v[p * 4 + 0] = t.x; v[p * 4 + 1] = t.y;
        v[p * 4 + 2] = t.z; v[p * 4 + 3] = t.w;
    }
}
__device__ __forceinline__ void p_sts(const float* v, __half* Shi, __half* Slo, int tid)
{
#pragma unroll
    for (int p = 0; p < 4; ++p) {
        __half h[4], l[4];
#pragma unroll
        for (int j = 0; j < 4; ++j) split_h(v[p * 4 + j], h[j], l[j]);
        const int idx = tid + p * 256;
        const int r = idx >> 3, c = (idx & 7) * 4;
        *reinterpret_cast<__half2*>(&Shi[r * PROWH + c])     = __halves2half2(h[0], h[1]);
        *reinterpret_cast<__half2*>(&Shi[r * PROWH + c + 2]) = __halves2half2(h[2], h[3]);
        *reinterpret_cast<__half2*>(&Slo[r * PROWH + c])     = __halves2half2(l[0], l[1]);
        *reinterpret_cast<__half2*>(&Slo[r * PROWH + c + 2]) = __halves2half2(l[2], l[3]);
    }
}

__global__ __launch_bounds__(256)
void proj_both(const float* __restrict__ Vf, const float* __restrict__ Lf,
               const float* __restrict__ Wv, const float* __restrict__ bv,
               const float* __restrict__ Wl, const float* __restrict__ bl,
               __half* __restrict__ vph, __half* __restrict__ vpl,
               __half* __restrict__ lph, __half* __restrict__ lpl)
{
    extern __shared__ __half hsm[];
    const int z = blockIdx.z;
    const float* A    = z ? Lf : Vf;
    const float* B    = z ? Wl : Wv;
    const float* bias = z ? bl : bv;
    __half* Ch = z ? lph : vph;
    __half* Cl = z ? lpl : vpl;

    const int tid  = threadIdx.x;
    const int lane = tid & 31;
    const int wid  = tid >> 5;
    const int wm   = wid & 3;
    const int wn   = wid >> 2;
    const long m0  = (long)blockIdx.y * 128;
    const long n0  = (long)blockIdx.x * 128;
    const int lr   = lane >> 2;
    const int lc   = lane & 3;

    float acc[2][8][4];
#pragma unroll
    for (int i = 0; i < 2; ++i)
#pragma unroll
        for (int j = 0; j < 8; ++j)
#pragma unroll
            for (int q = 0; q < 4; ++q) acc[i][j][q] = 0.f;

    const int NIT = DIM / 32;   // 24
    float ra[16], rb[16];

    p_ldg(A, DIM, m0, 0, tid, ra);
    p_ldg(B, DIM, n0, 0, tid, rb);
    p_sts(ra, hsm,               hsm + PTILE_H,     tid);
    p_sts(rb, hsm + 2 * PTILE_H, hsm + 3 * PTILE_H, tid);
    p_ldg(A, DIM, m0, 32, tid, ra);
    p_ldg(B, DIM, n0, 32, tid, rb);

    for (int it = 0; it < NIT; ++it) {
        __syncthreads();
        if (it + 1 < NIT) {
            __half* st = hsm + ((it + 1) % 3) * PSTAGE_H;
            p_sts(ra, st,               st + PTILE_H,     tid);
            p_sts(rb, st + 2 * PTILE_H, st + 3 * PTILE_H, tid);
        }
        if (it + 2 < NIT) {
            p_ldg(A, DIM, m0, (it + 2) * 32, tid, ra);
            p_ldg(B, DIM, n0, (it + 2) * 32, tid, rb);
        }
        const __half* Ahi = hsm + (it % 3) * PSTAGE_H;
        const __half* Alo = Ahi + PTILE_H;
        const __half* Bhi = Ahi + 2 * PTILE_H;
        const __half* Blo = Ahi + 3 * PTILE_H;

#pragma unroll
        for (int ks = 0; ks < 2; ++ks) {
            const int kb = ks * 16;
            uint32_t ah[2][4], al[2][4];
#pragma unroll
            for (int mt = 0; mt < 2; ++mt) {
                const int mb = wm * 32 + mt * 16;
                const int o0 = (mb + lr)     * PROWH + kb + 2 * lc;
                const int o1 = (mb + 8 + lr) * PROWH + kb + 2 * lc;
                ah[mt][0] = lds_u32(&Ahi[o0]);
                ah[mt][1] = lds_u32(&Ahi[o1]);
                ah[mt][2] = lds_u32(&Ahi[o0 + 8]);
                ah[mt][3] = lds_u32(&Ahi[o1 + 8]);
                al[mt][0] = lds_u32(&Alo[o0]);
                al[mt][1] = lds_u32(&Alo[o1]);
                al[mt][2] = lds_u32(&Alo[o0 + 8]);
                al[mt][3] = lds_u32(&Alo[o1 + 8]);
            }
#pragma unroll
            for (int nt = 0; nt < 8; ++nt) {
                const int nb = wn * 64 + nt * 8;
                const int ob = (nb + lr) * PROWH + kb + 2 * lc;
                uint32_t bh[2], bl[2];
                bh[0] = lds_u32(&Bhi[ob]);
                bh[1] = lds_u32(&Bhi[ob + 8]);
                bl[0] = lds_u32(&Blo[ob]);
                bl[1] = lds_u32(&Blo[ob + 8]);
#pragma unroll
                for (int mt = 0; mt < 2; ++mt) {
                    mma16(acc[mt][nt], ah[mt], bh);
                    mma16(acc[mt][nt], ah[mt], bl);
                    mma16(acc[mt][nt], al[mt], bh);
                }
            }
        }
    }

    // epilogue: +bias, split to hi/lo fp16
#pragma unroll
    for (int mt = 0; mt < 2; ++mt) {
        const long r0 = m0 + wm * 32 + mt * 16 + lr;
#pragma unroll
        for (int nt = 0; nt < 8; ++nt) {
            const long c = n0 + wn * 64 + nt * 8 + lc * 2;
            float2 bb = *reinterpret_cast<const float2*>(&bias[c]);
            float v[4] = {acc[mt][nt][0] + bb.x, acc[mt][nt][1] + bb.y,
                          acc[mt][nt][2] + bb.x, acc[mt][nt][3] + bb.y};
            __half h[4], l[4];
#pragma unroll
            for (int q = 0; q < 4; ++q) split_h(v[q], h[q], l[q]);
            *reinterpret_cast<__half2*>(&Ch[r0 * DIM + c])       = __halves2half2(h[0], h[1]);
            *reinterpret_cast<__half2*>(&Ch[(r0 + 8) * DIM + c]) = __halves2half2(h[2], h[3]);
            *reinterpret_cast<__half2*>(&Cl[r0 * DIM + c])       = __halves2half2(l[0], l[1]);
            *reinterpret_cast<__half2*>(&Cl[(r0 + 8) * DIM + c]) = __halves2half2(l[2], l[3]);
        }
    }
}

// ---------------------------------------------------------------------------
// GEMM kernel wrappers
// ---------------------------------------------------------------------------
// sim[b] = (vph+vpl)(lph+lpl)^T, 3x, fp32 out.  grid (16,16,8), smem 122880
__global__ __launch_bounds__(256)
void sim_gemm(const __half* __restrict__ vph, const __half* __restrict__ vpl,
              const __half* __restrict__ lph, const __half* __restrict__ lpl,
              float* __restrict__ sim)
{
    extern __shared__ __half hsm[];
    const long b  = blockIdx.z;
    const long sF = (long)SEQ * DIM;
    const long sS = (long)SEQ * SEQ;
    gemm16_body<true, true, 3, false, false>(
        vph + b * sF, vpl + b * sF, DIM,
        lph + b * sF, lpl + b * sF, DIM,
        sim + b * sS, nullptr, nullptr, SEQ, DIM, nullptr, hsm);
}

// av/al, 1x, writes comb16 hi/lo.  grid (6,16,16), smem 81920, 2 CTAs/SM
__global__ __launch_bounds__(256, 2)
void avl_gemm(const __half* __restrict__ at,  const __half* __restrict__ att,
              const __half* __restrict__ vpt, const __half* __restrict__ lpt,
              __half* __restrict__ cbh, __half* __restrict__ cbl)
{
    extern __shared__ __half hsm[];
    const int z   = blockIdx.z;
    const long b  = z & 7;
    const long sS = (long)SEQ * SEQ;
    const long sF = (long)SEQ * DIM;
    const long sO = (long)SEQ * 2 * DIM;
    const __half* A = (z >> 3) ? (att + b * sS) : (at + b * sS);
    const __half* B = (z >> 3) ? (lpt + b * sF) : (vpt + b * sF);
    const long    co = b * sO + ((z >> 3) ? DIM : 0);
    gemm16_body<false, false, 4, true, false>(
        A, nullptr, SEQ, B, nullptr, SEQ,
        nullptr, cbh + co, cbl + co, 2 * DIM, SEQ, nullptr, hsm);
}

// out = (cbh+cbl) @ Wo16^T + bo, 2x, fp32 out.  grid (6,128,1), smem 92160, 2 CTAs/SM
__global__ __launch_bounds__(256, 2)
void out_gemm(const __half* __restrict__ cbh, const __half* __restrict__ cbl,
              const __half* __restrict__ wo, const float* __restrict__ bo,
              float* __restrict__ out)
{
    extern __shared__ __half hsm[];
    gemm16_body<true, false, 3, false, true>(
        cbh, cbl, 2 * DIM, wo, nullptr, 2 * DIM,
        out, nullptr, nullptr, DIM, 2 * DIM, bo, hsm);
}

// ---------------------------------------------------------------------------
// fp16 tiled transpose: dst[b][x][y] = src[b][y][x].  src [R][C], dst [C][R].
// block (32,8), grid (C/32, R/32, BATCHES)
// ---------------------------------------------------------------------------
__global__ __launch_bounds__(256)
void transpose16(const __half* __restrict__ src, __half* __restrict__ dst,
                 int R, int C, long stride)
{
    __shared__ __half t[32][34];
    const long b  = blockIdx.z;
    const int  x0 = blockIdx.x * 32;
    const int  y0 = blockIdx.y * 32;
    const __half* s = src + b * stride;
    __half*       d = dst + b * stride;
    const int tx = threadIdx.x, ty = threadIdx.y;
#pragma unroll
    for (int i = 0; i < 4; ++i)
        t[ty + i * 8][tx] = s[(long)(y0 + ty + i * 8) * C + x0 + tx];
    __syncthreads();
#pragma unroll
    for (int i = 0; i < 4; ++i)
        d[(long)(x0 + ty + i * 8) * R + y0 + tx] = t[tx][ty + i * 8];
}

// Wo fp32 -> fp16
__global__ __launch_bounds__(256)
void wo_convert(const float* __restrict__ Wo, __half* __restrict__ wo16)
{
    const int i = blockIdx.x * 256 + threadIdx.x;
    float2 v = *reinterpret_cast<const float2*>(&Wo[i * 2]);
    *reinterpret_cast<__half2*>(&wo16[i * 2]) = __floats2half2_rn(v.x, v.y);
}

// ---------------------------------------------------------------------------
// Row softmax: sim fp32 -> attn fp16. One block per row of 2048.
// ---------------------------------------------------------------------------
__global__ __launch_bounds__(256)
void softmax2048h(const float* __restrict__ S, __half* __restrict__ O)
{
    const float* p = S + (long)blockIdx.x * 2048;
    __half*      o = O + (long)blockIdx.x * 2048;
    const int tid = threadIdx.x;

    float4 v0 = reinterpret_cast<const float4*>(p)[tid];
    float4 v1 = reinterpret_cast<const float4*>(p)[tid + 256];

    float mx = fmaxf(fmaxf(fmaxf(v0.x, v0.y), fmaxf(v0.z, v0.w)),
                     fmaxf(fmaxf(v1.x, v1.y), fmaxf(v1.z, v1.w)));

    __shared__ float red[8];
#pragma unroll
    for (int ofs = 16; ofs > 0; ofs >>= 1) mx = fmaxf(mx, __shfl_xor_sync(0xffffffffu, mx, ofs));
    if ((tid & 31) == 0) red[tid >> 5] = mx;
    __syncthreads();
    if (tid == 0) {
        float m = red[0];
#pragma unroll
        for (int w = 1; w < 8; ++w) m = fmaxf(m, red[w]);
        red[0] = m;
    }
    __syncthreads();
    mx = red[0];
    __syncthreads();

    v0.x = __expf(v0.x - mx); v0.y = __expf(v0.y - mx);
    v0.z = __expf(v0.z - mx); v0.w = __expf(v0.w - mx);
    v1.x = __expf(v1.x - mx); v1.y = __expf(v1.y - mx);
    v1.z = __expf(v1.z - mx); v1.w = __expf(v1.w - mx);

    float s = (v0.x + v0.y + v0.z + v0.w) + (v1.x + v1.y + v1.z + v1.w);
#pragma unroll
    for (int ofs = 16; ofs > 0; ofs >>= 1) s += __shfl_xor_sync(0xffffffffu, s, ofs);
    if ((tid & 31) == 0) red[tid >> 5] = s;
    __syncthreads();
    if (tid == 0) {
        float t = 0.f;
#pragma unroll
        for (int w = 0; w < 8; ++w) t += red[w];
        red[0] = t;
    }
    __syncthreads();
    const float inv = 1.0f / red[0];

    uint2 o0, o1;
    *reinterpret_cast<__half2*>(&o0.x) = __floats2half2_rn(v0.x * inv, v0.y * inv);
    *reinterpret_cast<__half2*>(&o0.y) = __floats2half2_rn(v0.z * inv, v0.w * inv);
    *reinterpret_cast<__half2*>(&o1.x) = __floats2half2_rn(v1.x * inv, v1.y * inv);
    *reinterpret_cast<__half2*>(&o1.y) = __floats2half2_rn(v1.z * inv, v1.w * inv);
    reinterpret_cast<uint2*>(o)[tid]       = o0;
    reinterpret_cast<uint2*>(o)[tid + 256] = o1;
}

// ---------------------------------------------------------------------------
// Launch
// ---------------------------------------------------------------------------
extern "C" void kernel_launch(void* const* d_in, const int* in_sizes, int n_in,
                              void* d_out, int out_size)
{
    const float* Vf = (const float*)d_in[0];
    const float* Lf = (const float*)d_in[1];
    const float* Wv = (const float*)d_in[2];
    const float* bv = (const float*)d_in[3];
    const float* Wl = (const float*)d_in[4];
    const float* bl = (const float*)d_in[5];
    const float* Wo = (const float*)d_in[6];
    const float* bo = (const float*)d_in[7];
    float* out = (float*)d_out;

    __half *vph, *vpl, *lph, *lpl, *vpt, *lpt, *at, *att, *cbh, *cbl, *wo16;
    float* sim;
    cudaGetSymbolAddress((void**)&vph, g_vph);
    cudaGetSymbolAddress((void**)&vpl, g_vpl);
    cudaGetSymbolAddress((void**)&lph, g_lph);
    cudaGetSymbolAddress((void**)&lpl, g_lpl);
    cudaGetSymbolAddress((void**)&vpt, g_vpt);
    cudaGetSymbolAddress((void**)&lpt, g_lpt);
    cudaGetSymbolAddress((void**)&sim, g_sim);
    cudaGetSymbolAddress((void**)&at,  g_at);
    cudaGetSymbolAddress((void**)&att, g_att);
    cudaGetSymbolAddress((void**)&cbh, g_cbh);
    cudaGetSymbolAddress((void**)&cbl, g_cbl);
    cudaGetSymbolAddress((void**)&wo16, g_wo16);

    cudaFuncSetAttribute(proj_both, cudaFuncAttributeMaxDynamicSharedMemorySize, PSMEM_B);
    cudaFuncSetAttribute(sim_gemm,  cudaFuncAttributeMaxDynamicSharedMemorySize, 4 * TILE16 * 3 * 2);
    cudaFuncSetAttribute(avl_gemm,  cudaFuncAttributeMaxDynamicSharedMemorySize, 2 * TILE16 * 4 * 2);
    cudaFuncSetAttribute(out_gemm,  cudaFuncAttributeMaxDynamicSharedMemorySize, 3 * TILE16 * 3 * 2);

    const dim3 blk(256);
    const long sF = (long)SEQ * DIM;
    const long sS = (long)SEQ * SEQ;

    // Wo fp16 (independent)
    wo_convert<<<DIM * 2 * DIM / 512, blk>>>(Wo, wo16);
    // projections -> vp/lp hi+lo fp16
    proj_both<<<dim3(DIM/128, TOK/128, 2), blk, PSMEM_B>>>(
        Vf, Lf, Wv, bv, Wl, bl, vph, vpl, lph, lpl);
    // transposed fp16 copies for av/al
    transpose16<<<dim3(DIM/32, SEQ/32, BATCH), dim3(32, 8)>>>(vph, vpt, SEQ, DIM, sF);
    transpose16<<<dim3(DIM/32, SEQ/32, BATCH), dim3(32, 8)>>>(lph, lpt, SEQ, DIM, sF);
    // sim (3x)
    sim_gemm<<<dim3(SEQ/128, SEQ/128, BATCH), blk, 4 * TILE16 * 3 * 2>>>(
        vph, vpl, lph, lpl, sim);
    // softmax -> attn fp16
    softmax2048h<<<TOK, blk>>>(sim, at);
    // attn^T fp16
    transpose16<<<dim3(SEQ/32, SEQ/32, BATCH), dim3(32, 8)>>>(at, att, SEQ, SEQ, sS);
    // av + al (1x) -> comb16 hi/lo
    avl_gemm<<<dim3(DIM/128, SEQ/128, 2 * BATCH), blk, 2 * TILE16 * 4 * 2>>>(
        at, att, vpt, lpt, cbh, cbl);
    // out (2x)
    out_gemm<<<dim3(DIM/128, TOK/128, 1), blk, 3 * TILE16 * 3 * 2>>>(
        cbh, cbl, wo16, bo, out);
}